// round 13
// baseline (speedup 1.0000x reference)
#include <cuda_runtime.h>
#include <cuda_fp16.h>
#include <math.h>
#include <stdint.h>

#define BB 16
#define NN 1024
#define CC 768
#define NH 12
#define HD 64
#define ROWS (BB*NN)        // 16384

// GEMM tiling: block 128x128, BK=64, 3-stage cp.async, 8 warps 2x4 (warp 64x32)
#define BM 128
#define BN 128
#define BK 64
#define PITCH 72            // fp16 elems per smem row (144B): ldmatrix conflict-free, 16B aligned
#define NSTAGE 3
#define PLANE_EL (128*PITCH)                 // 9216
#define STAGE_EL (2*PLANE_EL)                // 18432 (A + B)
#define GEMM_SMEM (NSTAGE*STAGE_EL*2)        // 110592 B -> 2 CTAs/SM (221KB < 228KB)
#define GTHREADS 256

// ---------------- device scratch ----------------
__device__ float g_eta[BB*NH*NN];
__device__ float g_x2[ROWS*CC];
__device__ float g_qkvbias[3*CC];
__device__ __align__(16) __half g_qkv[ROWS*3*CC];   // qkv fp16
__device__ __align__(16) __half g_h[ROWS*CC];
__device__ __align__(16) __half g_attn[ROWS*CC];
__device__ __align__(16) __half g_act[ROWS*4*CC];
__device__ __align__(16) __half g_wq[3*CC*CC];
__device__ __align__(16) __half g_wp[CC*CC];
__device__ __align__(16) __half g_w1[4*CC*CC];
__device__ __align__(16) __half g_w2[CC*4*CC];

// ---------------- helpers ----------------
__device__ __forceinline__ float warpsum(float v) {
#pragma unroll
    for (int o = 16; o > 0; o >>= 1) v += __shfl_xor_sync(0xffffffffu, v, o);
    return v;
}
__device__ __forceinline__ void mma16816(float* d, const uint32_t* a, const uint32_t* b) {
    asm volatile(
        "mma.sync.aligned.m16n8k16.row.col.f32.f16.f16.f32 "
        "{%0,%1,%2,%3}, {%4,%5,%6,%7}, {%8,%9}, {%0,%1,%2,%3};"
        : "+f"(d[0]), "+f"(d[1]), "+f"(d[2]), "+f"(d[3])
        : "r"(a[0]), "r"(a[1]), "r"(a[2]), "r"(a[3]), "r"(b[0]), "r"(b[1]));
}
__device__ __forceinline__ void cpasync16(uint32_t dst, const void* src) {
    asm volatile("cp.async.cg.shared.global [%0], [%1], 16;" :: "r"(dst), "l"(src));
}
__device__ __forceinline__ uint32_t smaddr(const void* p) {
    uint32_t a;
    asm("{ .reg .u64 t; cvta.to.shared.u64 t, %1; cvt.u32.u64 %0, t; }" : "=r"(a) : "l"(p));
    return a;
}
__device__ __forceinline__ void ldm_x4(uint32_t* r, uint32_t addr) {
    asm volatile("ldmatrix.sync.aligned.m8n8.x4.shared.b16 {%0,%1,%2,%3}, [%4];"
        : "=r"(r[0]), "=r"(r[1]), "=r"(r[2]), "=r"(r[3]) : "r"(addr));
}

// ---------------- small elementwise kernels ----------------
__global__ void qkvbias_kernel(const float* __restrict__ qb,
                               const float* __restrict__ vb,
                               float* __restrict__ out) {
    int i = blockIdx.x * blockDim.x + threadIdx.x;
    if (i < 3*CC) out[i] = (i < CC) ? qb[i] : (i < 2*CC ? 0.0f : vb[i - 2*CC]);
}
#define WQ_N (3*CC*CC)
#define WP_N (CC*CC)
#define W1_N (4*CC*CC)
#define W2_N (CC*4*CC)
__global__ void convert_w(const float* __restrict__ qkv_w, const float* __restrict__ proj_w,
                          const float* __restrict__ fc1_w, const float* __restrict__ fc2_w,
                          __half* __restrict__ wq, __half* __restrict__ wp,
                          __half* __restrict__ w1, __half* __restrict__ w2) {
    int i = blockIdx.x * blockDim.x + threadIdx.x;
    if (i < WQ_N) wq[i] = __float2half_rn(qkv_w[i]);
    else if (i < WQ_N + WP_N) { int j = i - WQ_N; wp[j] = __float2half_rn(proj_w[j]); }
    else if (i < WQ_N + WP_N + W1_N) { int j = i - WQ_N - WP_N; w1[j] = __float2half_rn(fc1_w[j]); }
    else if (i < WQ_N + WP_N + W1_N + W2_N) { int j = i - WQ_N - WP_N - W1_N; w2[j] = __float2half_rn(fc2_w[j]); }
}

// ---------------- LayerNorm, warp-per-row (+ optional eta), fp16 out ----------------
__global__ void __launch_bounds__(256) ln_kernel(
    const float* __restrict__ x, const float* __restrict__ w, const float* __restrict__ bp,
    const float* __restrict__ lrw, const float* __restrict__ lrb,
    __half* __restrict__ hout, float* __restrict__ eta)
{
    int lane = threadIdx.x & 31, warp = threadIdx.x >> 5;
    int row = blockIdx.x * 8 + warp;
    const float4* xr = (const float4*)(x + (size_t)row * CC);

    float4 v[6];
    float s = 0.f;
#pragma unroll
    for (int j = 0; j < 6; j++) {
        v[j] = xr[j*32 + lane];
        s += v[j].x + v[j].y + v[j].z + v[j].w;
    }
    float mu = warpsum(s) * (1.0f/CC);
    float vs = 0.f;
#pragma unroll
    for (int j = 0; j < 6; j++) {
        v[j].x -= mu; v[j].y -= mu; v[j].z -= mu; v[j].w -= mu;
        vs += v[j].x*v[j].x + v[j].y*v[j].y + v[j].z*v[j].z + v[j].w*v[j].w;
    }
    float rstd = rsqrtf(warpsum(vs) * (1.0f/CC) + 1e-6f);

    const float4* wv = (const float4*)w;
    const float4* bv = (const float4*)bp;
    float h[24];
#pragma unroll
    for (int j = 0; j < 6; j++) {
        float4 ww = wv[j*32 + lane], bb = bv[j*32 + lane];
        h[j*4+0] = ww.x * v[j].x * rstd + bb.x;
        h[j*4+1] = ww.y * v[j].y * rstd + bb.y;
        h[j*4+2] = ww.z * v[j].z * rstd + bb.z;
        h[j*4+3] = ww.w * v[j].w * rstd + bb.w;
    }
    __half* hr = hout + (size_t)row * CC;
#pragma unroll
    for (int j = 0; j < 6; j++) {
        __half2 a = __floats2half2_rn(h[j*4+0], h[j*4+1]);
        __half2 b = __floats2half2_rn(h[j*4+2], h[j*4+3]);
        *(uint2*)&hr[(j*32 + lane)*4] = make_uint2(*(uint32_t*)&a, *(uint32_t*)&b);
    }

    if (eta) {
#pragma unroll
        for (int hh = 0; hh < NH; hh++) {
            const float4* lw = (const float4*)(lrw + (size_t)hh * CC);
            float p = 0.f;
#pragma unroll
            for (int j = 0; j < 6; j++) {
                float4 l4 = lw[j*32 + lane];
                p += h[j*4+0]*l4.x + h[j*4+1]*l4.y + h[j*4+2]*l4.z + h[j*4+3]*l4.w;
            }
            p = warpsum(p);
            if (lane == hh) {
                p += lrb[hh];
                float sg = 1.0f / (1.0f + expf(-p));
                int b = row >> 10, n = row & 1023;
                eta[((size_t)(b*NH + hh))*NN + n] = sg * (1.0f/HD);
            }
        }
    }
}

// ---------------- cp.async + ldmatrix 3-stage BK=64 fp16 GEMM NT ----------------
// block 128x128, 8 warps 2x4, warp tile 64x32
// EPI: 0 = fp32 out; 1 = +Res fp32 out; 2 = gelu fp16 out; 3 = plain fp16 out
template<int EPI>
__global__ void __launch_bounds__(GTHREADS, 2) gemm_mma(
    const __half* __restrict__ A, const __half* __restrict__ Bw,
    const float* __restrict__ bias, const float* __restrict__ Res,
    float* __restrict__ Cout, __half* __restrict__ Ch,
    int M, int Nn, int K)
{
    extern __shared__ __half smem[];
    uint32_t smbase = smaddr(smem);

    int tid = threadIdx.x;
    int lane = tid & 31, wid = tid >> 5;
    int wm = wid & 1, wn = wid >> 1;          // 2x4 warp grid, warp tile 64x32
    int g = lane >> 2, t4 = lane & 3;
    int bn = blockIdx.x * BN, bm = blockIdx.y * BM;
    const int nch = K / BK;

    const __half* Ag = A  + (size_t)bm*K;
    const __half* Bg = Bw + (size_t)bn*K;

    int aRow = (wm*64 + (lane & 15))*PITCH + (lane >> 4)*8;
    int bRow = (wn*32 + (lane >> 4)*8 + (lane & 7))*PITCH + ((lane >> 3) & 1)*8;

    float acc[4][4][4];
#pragma unroll
    for (int i = 0; i < 4; i++)
#pragma unroll
        for (int j = 0; j < 4; j++)
#pragma unroll
            for (int k = 0; k < 4; k++) acc[i][j][k] = 0.f;

#define ISSUE(stage, c) do {                                                    \
        int kb = (c) * BK;                                                      \
        uint32_t sb = smbase + ((stage)*STAGE_EL)*2;                            \
        _Pragma("unroll")                                                       \
        for (int it = 0; it < 4; it++) {                                        \
            int u = tid + it*256;                                               \
            int r0_ = u >> 3, s0_ = u & 7;                                      \
            cpasync16(sb + (r0_*PITCH + s0_*8)*2,                               \
                      Ag + (size_t)r0_*K + kb + s0_*8);                         \
            cpasync16(sb + (PLANE_EL + r0_*PITCH + s0_*8)*2,                    \
                      Bg + (size_t)r0_*K + kb + s0_*8);                         \
        }                                                                       \
        asm volatile("cp.async.commit_group;" ::: "memory");                    \
    } while (0)

    ISSUE(0, 0);
    ISSUE(1, 1);

    for (int c = 0; c < nch; ++c) {
        int s = c % NSTAGE;
        // oldest outstanding group = chunk c; allow 1 newer group in flight
        asm volatile("cp.async.wait_group 1;" ::: "memory");
        __syncthreads();
        if (c + 2 < nch) ISSUE((c + 2) % NSTAGE, c + 2);

        uint32_t pA = smbase + (s*STAGE_EL)*2;
        uint32_t pB = smbase + (s*STAGE_EL + PLANE_EL)*2;

#pragma unroll
        for (int ks = 0; ks < 4; ks++) {
            int kof = ks*16;
            uint32_t ah[4][4], bh[4][2];
#pragma unroll
            for (int mb = 0; mb < 4; mb++)
                ldm_x4(ah[mb], pA + (aRow + mb*16*PITCH + kof)*2);
#pragma unroll
            for (int p = 0; p < 2; p++) {
                uint32_t r[4];
                ldm_x4(r, pB + (bRow + p*16*PITCH + kof)*2);
                bh[2*p][0] = r[0]; bh[2*p][1] = r[1]; bh[2*p+1][0] = r[2]; bh[2*p+1][1] = r[3];
            }
#pragma unroll
            for (int mt = 0; mt < 4; mt++)
#pragma unroll
                for (int nt = 0; nt < 4; nt++) mma16816(acc[mt][nt], ah[mt], bh[nt]);
        }
    }
#undef ISSUE

    // epilogue
#pragma unroll
    for (int mt = 0; mt < 4; mt++) {
#pragma unroll
        for (int nt = 0; nt < 4; nt++) {
            int r0 = bm + wm*64 + mt*16 + g;
            int c0 = bn + wn*32 + nt*8 + t4*2;
            float b0 = bias[c0], b1 = bias[c0+1];
#pragma unroll
            for (int half = 0; half < 2; half++) {
                int r = r0 + half*8;
                size_t gi = (size_t)r * Nn + c0;
                float v0 = acc[mt][nt][half*2]     + b0;
                float v1 = acc[mt][nt][half*2 + 1] + b1;
                if (EPI == 1) { v0 += Res[gi]; v1 += Res[gi+1]; }
                if (EPI == 2) {
                    v0 = 0.5f*v0*(1.0f + erff(v0*0.70710678118654752f));
                    v1 = 0.5f*v1*(1.0f + erff(v1*0.70710678118654752f));
                }
                if (EPI == 2 || EPI == 3) {
                    __half2 hv = __floats2half2_rn(v0, v1);
                    *(uint32_t*)&Ch[gi] = *(uint32_t*)&hv;
                } else {
                    Cout[gi]   = v0;
                    Cout[gi+1] = v1;
                }
            }
        }
    }
}

// ---------------- TTT kernel: one block per (b,h), 4x4 register-tiled GEMMs ----------------
__global__ void __launch_bounds__(256) ttt_kernel(
    const __half* __restrict__ qkv, const float* __restrict__ eta,
    const float* __restrict__ W1g, const float* __restrict__ b1g,
    const float* __restrict__ tttw, const float* __restrict__ tttb,
    __half* __restrict__ attn)
{
    extern __shared__ float sm[];
    float* sW1  = sm;            // 4096 (becomes W1_bar)
    float* sK   = sm + 4096;
    float* sV   = sm + 8192;
    float* sZ   = sm + 12288;
    float* sEta = sm + 16384;    // 64
    float* sGw  = sEta + 64;
    float* sGb  = sGw + 64;
    float* sB1  = sGb + 64;
    float* sB1b = sB1 + 64;

    int bh = blockIdx.x;
    int b = bh / NH, h = bh % NH;
    int tid = threadIdx.x;
    int lane = tid & 31, warp = tid >> 5;
    int tg = tid >> 4;
    int tc = (tid & 15) * 4;

    for (int i = tid; i < 4096; i += 256) sW1[i] = W1g[h*4096 + i];
    if (tid < 64) {
        sGw[tid] = tttw[h*64 + tid];
        sGb[tid] = tttb[h*64 + tid];
        sB1[tid] = b1g[h*64 + tid];
    }
    __syncthreads();

    const size_t rs = 3*CC;
    const __half* qbase = qkv + (size_t)b*NN*rs + 0*CC + h*HD;
    const __half* kbase = qkv + (size_t)b*NN*rs + 1*CC + h*HD;
    const __half* vbase = qkv + (size_t)b*NN*rs + 2*CC + h*HD;

    float accW[4][4];
#pragma unroll
    for (int i = 0; i < 4; i++)
#pragma unroll
        for (int j = 0; j < 4; j++) accW[i][j] = 0.f;
    float accB[4] = {0.f, 0.f, 0.f, 0.f};

    for (int c = 0; c < 16; c++) {
        int n0 = c * 64;
        for (int i = tid; i < 2048; i += 256) {
            int n = i >> 5, e2 = (i & 31) * 2;
            float2 kf = __half22float2(*(const __half2*)&kbase[(size_t)(n0+n)*rs + e2]);
            float2 vf = __half22float2(*(const __half2*)&vbase[(size_t)(n0+n)*rs + e2]);
            sK[n*64 + e2] = kf.x; sK[n*64 + e2 + 1] = kf.y;
            sV[n*64 + e2] = vf.x; sV[n*64 + e2 + 1] = vf.y;
        }
        if (tid < 64) sEta[tid] = eta[(size_t)bh*NN + n0 + tid];
        __syncthreads();

        {
            float az[4][4];
#pragma unroll
            for (int i = 0; i < 4; i++)
#pragma unroll
                for (int j = 0; j < 4; j++) az[i][j] = sB1[tc+j];
            for (int d = 0; d < 64; d += 4) {
                float4 k4[4], w4[4];
#pragma unroll
                for (int i = 0; i < 4; i++) k4[i] = *(const float4*)&sK[(tg*4+i)*64 + d];
#pragma unroll
                for (int dd = 0; dd < 4; dd++) w4[dd] = *(const float4*)&sW1[(d+dd)*64 + tc];
#pragma unroll
                for (int i = 0; i < 4; i++) {
                    const float* kk = (const float*)&k4[i];
#pragma unroll
                    for (int dd = 0; dd < 4; dd++) {
                        const float* ww = (const float*)&w4[dd];
#pragma unroll
                        for (int j = 0; j < 4; j++) az[i][j] += kk[dd] * ww[j];
                    }
                }
            }
#pragma unroll
            for (int i = 0; i < 4; i++)
#pragma unroll
                for (int j = 0; j < 4; j++) sZ[(tg*4+i)*64 + tc + j] = az[i][j];
        }
        __syncthreads();

        for (int j = 0; j < 8; j++) {
            int n = warp + 8*j;
            float z0 = sZ[n*64 + lane], z1 = sZ[n*64 + lane + 32];
            float mu = warpsum(z0 + z1) * (1.0f/64);
            float d0 = z0 - mu, d1 = z1 - mu;
            float var = warpsum(d0*d0 + d1*d1) * (1.0f/64);
            float rstd = rsqrtf(var + 1e-6f);
            float xh0 = d0*rstd, xh1 = d1*rstd;
            float t0 = sV[n*64 + lane]      - sK[n*64 + lane];
            float t1 = sV[n*64 + lane + 32] - sK[n*64 + lane + 32];
            float g0 = sGw[lane], g1 = sGw[lane + 32];
            float gho0 = (g0*xh0 + sGb[lane]      - t0) * g0;
            float gho1 = (g1*xh1 + sGb[lane + 32] - t1) * g1;
            float sg  = warpsum(gho0 + gho1);
            float sgx = warpsum(gho0*xh0 + gho1*xh1);
            float e = sEta[n];
            float inv = rstd * (1.0f/64) * e;
            sZ[n*64 + lane]      = (64.f*gho0 - sg - xh0*sgx) * inv;
            sZ[n*64 + lane + 32] = (64.f*gho1 - sg - xh1*sgx) * inv;
        }
        __syncthreads();

        for (int n = 0; n < 64; n++) {
            float4 k4 = *(const float4*)&sK[n*64 + tg*4];
            float4 e4 = *(const float4*)&sZ[n*64 + tc];
            const float* kk = (const float*)&k4;
            const float* ee = (const float*)&e4;
#pragma unroll
            for (int i = 0; i < 4; i++)
#pragma unroll
                for (int j = 0; j < 4; j++) accW[i][j] += kk[i] * ee[j];
            if (tg == 0) {
#pragma unroll
                for (int j = 0; j < 4; j++) accB[j] += ee[j];
            }
        }
        __syncthreads();
    }

#pragma unroll
    for (int i = 0; i < 4; i++)
#pragma unroll
        for (int j = 0; j < 4; j++) sW1[(tg*4+i)*64 + tc + j] -= accW[i][j];
    if (tg == 0) {
#pragma unroll
        for (int j = 0; j < 4; j++) sB1b[tc+j] = sB1[tc+j] - accB[j];
    }
    __syncthreads();

    for (int c = 0; c < 16; c++) {
        int n0 = c * 64;
        for (int i = tid; i < 2048; i += 256) {
            int n = i >> 5, e2 = (i & 31) * 2;
            float2 qf = __half22float2(*(const __half2*)&qbase[(size_t)(n0+n)*rs + e2]);
            sK[n*64 + e2] = qf.x; sK[n*64 + e2 + 1] = qf.y;
        }
        __syncthreads();
        {
            float az[4][4];
#pragma unroll
            for (int i = 0; i < 4; i++)
#pragma unroll
                for (int j = 0; j < 4; j++) az[i][j] = sB1b[tc+j];
            for (int d = 0; d < 64; d += 4) {
                float4 k4[4], w4[4];
#pragma unroll
                for (int i = 0; i < 4; i++) k4[i] = *(const float4*)&sK[(tg*4+i)*64 + d];
#pragma unroll
                for (int dd = 0; dd < 4; dd++) w4[dd] = *(const float4*)&sW1[(d+dd)*64 + tc];
#pragma unroll
                for (int i = 0; i < 4; i++) {
                    const float* kk = (const float*)&k4[i];
#pragma unroll
                    for (int dd = 0; dd < 4; dd++) {
                        const float* ww = (const float*)&w4[dd];
#pragma unroll
                        for (int j = 0; j < 4; j++) az[i][j] += kk[dd] * ww[j];
                    }
                }
            }
#pragma unroll
            for (int i = 0; i < 4; i++)
#pragma unroll
                for (int j = 0; j < 4; j++) sZ[(tg*4+i)*64 + tc + j] = az[i][j];
        }
        __syncthreads();
        for (int j = 0; j < 8; j++) {
            int n = warp + 8*j;
            float z0 = sZ[n*64 + lane], z1 = sZ[n*64 + lane + 32];
            float mu = warpsum(z0 + z1) * (1.0f/64);
            float d0 = z0 - mu, d1 = z1 - mu;
            float var = warpsum(d0*d0 + d1*d1) * (1.0f/64);
            float rstd = rsqrtf(var + 1e-6f);
            float o0 = sK[n*64 + lane]      + sGw[lane]     *d0*rstd + sGb[lane];
            float o1 = sK[n*64 + lane + 32] + sGw[lane + 32]*d1*rstd + sGb[lane + 32];
            size_t orow = ((size_t)(b*NN + n0 + n))*CC + h*HD;
            attn[orow + lane]      = __float2half_rn(o0);
            attn[orow + lane + 32] = __float2half_rn(o1);
        }
        __syncthreads();
    }
}

// ---------------- launch ----------------
extern "C" void kernel_launch(void* const* d_in, const int* in_sizes, int n_in,
                              void* d_out, int out_size) {
    const float* x      = (const float*)d_in[0];
    const float* qkv_w  = (const float*)d_in[1];
    const float* q_bias = (const float*)d_in[2];
    const float* v_bias = (const float*)d_in[3];
    const float* proj_w = (const float*)d_in[4];
    const float* proj_b = (const float*)d_in[5];
    const float* lr_w   = (const float*)d_in[6];
    const float* lr_b   = (const float*)d_in[7];
    const float* W1     = (const float*)d_in[8];
    const float* b1     = (const float*)d_in[9];
    const float* ttt_w  = (const float*)d_in[10];
    const float* ttt_b  = (const float*)d_in[11];
    const float* n1w    = (const float*)d_in[12];
    const float* n1b    = (const float*)d_in[13];
    const float* n2w    = (const float*)d_in[14];
    const float* n2b    = (const float*)d_in[15];
    const float* fc1_w  = (const float*)d_in[16];
    const float* fc1_b  = (const float*)d_in[17];
    const float* fc2_w  = (const float*)d_in[18];
    const float* fc2_b  = (const float*)d_in[19];
    float* out = (float*)d_out;

    float *etap, *x2, *qbias;
    __half *qkvp, *hp, *attnp, *actp, *wq, *wp, *w1, *w2;
    cudaGetSymbolAddress((void**)&qkvp,  g_qkv);
    cudaGetSymbolAddress((void**)&etap,  g_eta);
    cudaGetSymbolAddress((void**)&x2,    g_x2);
    cudaGetSymbolAddress((void**)&qbias, g_qkvbias);
    cudaGetSymbolAddress((void**)&hp,    g_h);
    cudaGetSymbolAddress((void**)&attnp, g_attn);
    cudaGetSymbolAddress((void**)&actp,  g_act);
    cudaGetSymbolAddress((void**)&wq,    g_wq);
    cudaGetSymbolAddress((void**)&wp,    g_wp);
    cudaGetSymbolAddress((void**)&w1,    g_w1);
    cudaGetSymbolAddress((void**)&w2,    g_w2);

    const int TTT_SMEM = (16384 + 64*5) * 4;
    cudaFuncSetAttribute(ttt_kernel, cudaFuncAttributeMaxDynamicSharedMemorySize, TTT_SMEM);
    cudaFuncSetAttribute(gemm_mma<1>, cudaFuncAttributeMaxDynamicSharedMemorySize, GEMM_SMEM);
    cudaFuncSetAttribute(gemm_mma<2>, cudaFuncAttributeMaxDynamicSharedMemorySize, GEMM_SMEM);
    cudaFuncSetAttribute(gemm_mma<3>, cudaFuncAttributeMaxDynamicSharedMemorySize, GEMM_SMEM);

    const int WTOT = WQ_N + WP_N + W1_N + W2_N;
    convert_w<<<(WTOT + 255)/256, 256>>>(qkv_w, proj_w, fc1_w, fc2_w, wq, wp, w1, w2);
    qkvbias_kernel<<<(3*CC + 255)/256, 256>>>(q_bias, v_bias, qbias);

    // LN1 + eta (warp-per-row)
    ln_kernel<<<ROWS/8, 256>>>(x, n1w, n1b, lr_w, lr_b, hp, etap);
    // qkv = h @ qkv_w^T + qkvbias  (fp16 out)
    gemm_mma<3><<<dim3(3*CC/BN, ROWS/BM), GTHREADS, GEMM_SMEM>>>(
        hp, wq, qbias, nullptr, nullptr, qkvp, ROWS, 3*CC, CC);
    // TTT attention
    ttt_kernel<<<BB*NH, 256, TTT_SMEM>>>(qkvp, etap, W1, b1, ttt_w, ttt_b, attnp);
    // x2 = x + attn @ proj_w^T + proj_b
    gemm_mma<1><<<dim3(CC/BN, ROWS/BM), GTHREADS, GEMM_SMEM>>>(
        attnp, wp, proj_b, x, x2, nullptr, ROWS, CC, CC);
    // LN2
    ln_kernel<<<ROWS/8, 256>>>(x2, n2w, n2b, nullptr, nullptr, hp, nullptr);
    // act = gelu(h2 @ fc1_w^T + fc1_b)
    gemm_mma<2><<<dim3(4*CC/BN, ROWS/BM), GTHREADS, GEMM_SMEM>>>(
        hp, w1, fc1_b, nullptr, nullptr, actp, ROWS, 4*CC, CC);
    // out = x2 + act @ fc2_w^T + fc2_b
    gemm_mma<1><<<dim3(CC/BN, ROWS/BM), GTHREADS, GEMM_SMEM>>>(
        actp, w2, fc2_b, x2, out, nullptr, ROWS, CC, 4*CC);
}

// round 14
// speedup vs baseline: 1.0758x; 1.0758x over previous
#include <cuda_runtime.h>
#include <cuda_fp16.h>
#include <math.h>
#include <stdint.h>

#define BB 16
#define NN 1024
#define CC 768
#define NH 12
#define HD 64
#define ROWS (BB*NN)        // 16384

// GEMM tiling: block 128x128, BK=64, 2-stage cp.async, 8 warps 2x4 (warp 64x32)
#define BM 128
#define BN 128
#define BK 64
#define PITCH 72            // fp16 elems per smem row (144B): ldmatrix conflict-free, 16B aligned
#define PLANE_EL (128*PITCH)                 // 9216
#define STAGE_EL (2*PLANE_EL)                // 18432 (A + B)
#define GEMM_SMEM (2*STAGE_EL*2)             // 73728 B -> 2 CTAs/SM
#define GTHREADS 256

// ---------------- device scratch ----------------
__device__ float g_eta[BB*NH*NN];
__device__ float g_x2[ROWS*CC];
__device__ float g_qkvbias[3*CC];
__device__ float g_dW[BB*NH*HD*HD];   // TTT partial W accumulators
__device__ float g_db[BB*NH*HD];
__device__ __align__(16) __half g_qkv[ROWS*3*CC];   // qkv fp16
__device__ __align__(16) __half g_h[ROWS*CC];
__device__ __align__(16) __half g_attn[ROWS*CC];
__device__ __align__(16) __half g_act[ROWS*4*CC];
__device__ __align__(16) __half g_wq[3*CC*CC];
__device__ __align__(16) __half g_wp[CC*CC];
__device__ __align__(16) __half g_w1[4*CC*CC];
__device__ __align__(16) __half g_w2[CC*4*CC];

// ---------------- helpers ----------------
__device__ __forceinline__ float warpsum(float v) {
#pragma unroll
    for (int o = 16; o > 0; o >>= 1) v += __shfl_xor_sync(0xffffffffu, v, o);
    return v;
}
__device__ __forceinline__ void mma16816(float* d, const uint32_t* a, const uint32_t* b) {
    asm volatile(
        "mma.sync.aligned.m16n8k16.row.col.f32.f16.f16.f32 "
        "{%0,%1,%2,%3}, {%4,%5,%6,%7}, {%8,%9}, {%0,%1,%2,%3};"
        : "+f"(d[0]), "+f"(d[1]), "+f"(d[2]), "+f"(d[3])
        : "r"(a[0]), "r"(a[1]), "r"(a[2]), "r"(a[3]), "r"(b[0]), "r"(b[1]));
}
__device__ __forceinline__ void cpasync16(uint32_t dst, const void* src) {
    asm volatile("cp.async.cg.shared.global [%0], [%1], 16;" :: "r"(dst), "l"(src));
}
__device__ __forceinline__ uint32_t smaddr(const void* p) {
    uint32_t a;
    asm("{ .reg .u64 t; cvta.to.shared.u64 t, %1; cvt.u32.u64 %0, t; }" : "=r"(a) : "l"(p));
    return a;
}
__device__ __forceinline__ void ldm_x4(uint32_t* r, uint32_t addr) {
    asm volatile("ldmatrix.sync.aligned.m8n8.x4.shared.b16 {%0,%1,%2,%3}, [%4];"
        : "=r"(r[0]), "=r"(r[1]), "=r"(r[2]), "=r"(r[3]) : "r"(addr));
}

// ---------------- small elementwise kernels ----------------
__global__ void qkvbias_kernel(const float* __restrict__ qb,
                               const float* __restrict__ vb,
                               float* __restrict__ out) {
    int i = blockIdx.x * blockDim.x + threadIdx.x;
    if (i < 3*CC) out[i] = (i < CC) ? qb[i] : (i < 2*CC ? 0.0f : vb[i - 2*CC]);
}
#define WQ_N (3*CC*CC)
#define WP_N (CC*CC)
#define W1_N (4*CC*CC)
#define W2_N (CC*4*CC)
__global__ void convert_w(const float* __restrict__ qkv_w, const float* __restrict__ proj_w,
                          const float* __restrict__ fc1_w, const float* __restrict__ fc2_w,
                          __half* __restrict__ wq, __half* __restrict__ wp,
                          __half* __restrict__ w1, __half* __restrict__ w2) {
    int i = blockIdx.x * blockDim.x + threadIdx.x;
    if (i < WQ_N) wq[i] = __float2half_rn(qkv_w[i]);
    else if (i < WQ_N + WP_N) { int j = i - WQ_N; wp[j] = __float2half_rn(proj_w[j]); }
    else if (i < WQ_N + WP_N + W1_N) { int j = i - WQ_N - WP_N; w1[j] = __float2half_rn(fc1_w[j]); }
    else if (i < WQ_N + WP_N + W1_N + W2_N) { int j = i - WQ_N - WP_N - W1_N; w2[j] = __float2half_rn(fc2_w[j]); }
}

// ---------------- LayerNorm, warp-per-row (+ optional eta), fp16 out ----------------
__global__ void __launch_bounds__(256) ln_kernel(
    const float* __restrict__ x, const float* __restrict__ w, const float* __restrict__ bp,
    const float* __restrict__ lrw, const float* __restrict__ lrb,
    __half* __restrict__ hout, float* __restrict__ eta)
{
    int lane = threadIdx.x & 31, warp = threadIdx.x >> 5;
    int row = blockIdx.x * 8 + warp;
    const float4* xr = (const float4*)(x + (size_t)row * CC);

    float4 v[6];
    float s = 0.f;
#pragma unroll
    for (int j = 0; j < 6; j++) {
        v[j] = xr[j*32 + lane];
        s += v[j].x + v[j].y + v[j].z + v[j].w;
    }
    float mu = warpsum(s) * (1.0f/CC);
    float vs = 0.f;
#pragma unroll
    for (int j = 0; j < 6; j++) {
        v[j].x -= mu; v[j].y -= mu; v[j].z -= mu; v[j].w -= mu;
        vs += v[j].x*v[j].x + v[j].y*v[j].y + v[j].z*v[j].z + v[j].w*v[j].w;
    }
    float rstd = rsqrtf(warpsum(vs) * (1.0f/CC) + 1e-6f);

    const float4* wv = (const float4*)w;
    const float4* bv = (const float4*)bp;
    float h[24];
#pragma unroll
    for (int j = 0; j < 6; j++) {
        float4 ww = wv[j*32 + lane], bb = bv[j*32 + lane];
        h[j*4+0] = ww.x * v[j].x * rstd + bb.x;
        h[j*4+1] = ww.y * v[j].y * rstd + bb.y;
        h[j*4+2] = ww.z * v[j].z * rstd + bb.z;
        h[j*4+3] = ww.w * v[j].w * rstd + bb.w;
    }
    __half* hr = hout + (size_t)row * CC;
#pragma unroll
    for (int j = 0; j < 6; j++) {
        __half2 a = __floats2half2_rn(h[j*4+0], h[j*4+1]);
        __half2 b = __floats2half2_rn(h[j*4+2], h[j*4+3]);
        *(uint2*)&hr[(j*32 + lane)*4] = make_uint2(*(uint32_t*)&a, *(uint32_t*)&b);
    }

    if (eta) {
#pragma unroll
        for (int hh = 0; hh < NH; hh++) {
            const float4* lw = (const float4*)(lrw + (size_t)hh * CC);
            float p = 0.f;
#pragma unroll
            for (int j = 0; j < 6; j++) {
                float4 l4 = lw[j*32 + lane];
                p += h[j*4+0]*l4.x + h[j*4+1]*l4.y + h[j*4+2]*l4.z + h[j*4+3]*l4.w;
            }
            p = warpsum(p);
            if (lane == hh) {
                p += lrb[hh];
                float sg = 1.0f / (1.0f + expf(-p));
                int b = row >> 10, n = row & 1023;
                eta[((size_t)(b*NH + hh))*NN + n] = sg * (1.0f/HD);
            }
        }
    }
}

// ---------------- cp.async + ldmatrix 2-stage BK=64 fp16 GEMM NT ----------------
// block 128x128, 8 warps 2x4, warp tile 64x32
// EPI: 0 = fp32 out; 1 = +Res fp32 out; 2 = gelu fp16 out; 3 = plain fp16 out
template<int EPI>
__global__ void __launch_bounds__(GTHREADS, 2) gemm_mma(
    const __half* __restrict__ A, const __half* __restrict__ Bw,
    const float* __restrict__ bias, const float* __restrict__ Res,
    float* __restrict__ Cout, __half* __restrict__ Ch,
    int M, int Nn, int K)
{
    extern __shared__ __half smem[];
    uint32_t smbase = smaddr(smem);

    int tid = threadIdx.x;
    int lane = tid & 31, wid = tid >> 5;
    int wm = wid & 1, wn = wid >> 1;
    int g = lane >> 2, t4 = lane & 3;
    int bn = blockIdx.x * BN, bm = blockIdx.y * BM;
    const int nch = K / BK;

    const __half* Ag = A  + (size_t)bm*K;
    const __half* Bg = Bw + (size_t)bn*K;

    int aRow = (wm*64 + (lane & 15))*PITCH + (lane >> 4)*8;
    int bRow = (wn*32 + (lane >> 4)*8 + (lane & 7))*PITCH + ((lane >> 3) & 1)*8;

    float acc[4][4][4];
#pragma unroll
    for (int i = 0; i < 4; i++)
#pragma unroll
        for (int j = 0; j < 4; j++)
#pragma unroll
            for (int k = 0; k < 4; k++) acc[i][j][k] = 0.f;

#define ISSUE(stage, c) do {                                                    \
        int kb = (c) * BK;                                                      \
        uint32_t sb = smbase + ((stage)*STAGE_EL)*2;                            \
        _Pragma("unroll")                                                       \
        for (int it = 0; it < 4; it++) {                                        \
            int u = tid + it*256;                                               \
            int r0_ = u >> 3, s0_ = u & 7;                                      \
            cpasync16(sb + (r0_*PITCH + s0_*8)*2,                               \
                      Ag + (size_t)r0_*K + kb + s0_*8);                         \
            cpasync16(sb + (PLANE_EL + r0_*PITCH + s0_*8)*2,                    \
                      Bg + (size_t)r0_*K + kb + s0_*8);                         \
        }                                                                       \
        asm volatile("cp.async.commit_group;" ::: "memory");                    \
    } while (0)

    ISSUE(0, 0);

    for (int c = 0; c < nch; ++c) {
        int s = c & 1;
        asm volatile("cp.async.wait_group 0;" ::: "memory");
        __syncthreads();
        if (c + 1 < nch) ISSUE(s ^ 1, c + 1);

        uint32_t pA = smbase + (s*STAGE_EL)*2;
        uint32_t pB = smbase + (s*STAGE_EL + PLANE_EL)*2;

#pragma unroll
        for (int ks = 0; ks < 4; ks++) {
            int kof = ks*16;
            uint32_t ah[4][4], bh[4][2];
#pragma unroll
            for (int mb = 0; mb < 4; mb++)
                ldm_x4(ah[mb], pA + (aRow + mb*16*PITCH + kof)*2);
#pragma unroll
            for (int p = 0; p < 2; p++) {
                uint32_t r[4];
                ldm_x4(r, pB + (bRow + p*16*PITCH + kof)*2);
                bh[2*p][0] = r[0]; bh[2*p][1] = r[1]; bh[2*p+1][0] = r[2]; bh[2*p+1][1] = r[3];
            }
#pragma unroll
            for (int mt = 0; mt < 4; mt++)
#pragma unroll
                for (int nt = 0; nt < 4; nt++) mma16816(acc[mt][nt], ah[mt], bh[nt]);
        }
    }
#undef ISSUE

    // epilogue
#pragma unroll
    for (int mt = 0; mt < 4; mt++) {
#pragma unroll
        for (int nt = 0; nt < 4; nt++) {
            int r0 = bm + wm*64 + mt*16 + g;
            int c0 = bn + wn*32 + nt*8 + t4*2;
            float b0 = bias[c0], b1 = bias[c0+1];
#pragma unroll
            for (int half = 0; half < 2; half++) {
                int r = r0 + half*8;
                size_t gi = (size_t)r * Nn + c0;
                float v0 = acc[mt][nt][half*2]     + b0;
                float v1 = acc[mt][nt][half*2 + 1] + b1;
                if (EPI == 1) { v0 += Res[gi]; v1 += Res[gi+1]; }
                if (EPI == 2) {
                    v0 = 0.5f*v0*(1.0f + erff(v0*0.70710678118654752f));
                    v1 = 0.5f*v1*(1.0f + erff(v1*0.70710678118654752f));
                }
                if (EPI == 2 || EPI == 3) {
                    __half2 hv = __floats2half2_rn(v0, v1);
                    *(uint32_t*)&Ch[gi] = *(uint32_t*)&hv;
                } else {
                    Cout[gi]   = v0;
                    Cout[gi+1] = v1;
                }
            }
        }
    }
}

// ---------------- TTT pass 1: partial dW/db, 3 blocks per (b,h) ----------------
__global__ void __launch_bounds__(256) ttt_p1(
    const __half* __restrict__ qkv, const float* __restrict__ eta,
    const float* __restrict__ W1g, const float* __restrict__ b1g,
    const float* __restrict__ tttw, const float* __restrict__ tttb,
    float* __restrict__ dW, float* __restrict__ db)
{
    extern __shared__ float sm[];
    float* sW1  = sm;            // 4096
    float* sK   = sm + 4096;
    float* sV   = sm + 8192;
    float* sZ   = sm + 12288;
    float* sEta = sm + 16384;    // 64
    float* sGw  = sEta + 64;
    float* sGb  = sGw + 64;
    float* sB1  = sGb + 64;

    int bh = blockIdx.x / 3, part = blockIdx.x % 3;
    int clo = (part*16)/3, chi = ((part+1)*16)/3;
    int b = bh / NH, h = bh % NH;
    int tid = threadIdx.x;
    int lane = tid & 31, warp = tid >> 5;
    int tg = tid >> 4;
    int tc = (tid & 15) * 4;

    for (int i = tid; i < 4096; i += 256) sW1[i] = W1g[h*4096 + i];
    if (tid < 64) {
        sGw[tid] = tttw[h*64 + tid];
        sGb[tid] = tttb[h*64 + tid];
        sB1[tid] = b1g[h*64 + tid];
    }
    __syncthreads();

    const size_t rs = 3*CC;
    const __half* kbase = qkv + (size_t)b*NN*rs + 1*CC + h*HD;
    const __half* vbase = qkv + (size_t)b*NN*rs + 2*CC + h*HD;

    float accW[4][4];
#pragma unroll
    for (int i = 0; i < 4; i++)
#pragma unroll
        for (int j = 0; j < 4; j++) accW[i][j] = 0.f;
    float accB[4] = {0.f, 0.f, 0.f, 0.f};

    for (int c = clo; c < chi; c++) {
        int n0 = c * 64;
        for (int i = tid; i < 2048; i += 256) {
            int n = i >> 5, e2 = (i & 31) * 2;
            float2 kf = __half22float2(*(const __half2*)&kbase[(size_t)(n0+n)*rs + e2]);
            float2 vf = __half22float2(*(const __half2*)&vbase[(size_t)(n0+n)*rs + e2]);
            sK[n*64 + e2] = kf.x; sK[n*64 + e2 + 1] = kf.y;
            sV[n*64 + e2] = vf.x; sV[n*64 + e2 + 1] = vf.y;
        }
        if (tid < 64) sEta[tid] = eta[(size_t)bh*NN + n0 + tid];
        __syncthreads();

        {
            float az[4][4];
#pragma unroll
            for (int i = 0; i < 4; i++)
#pragma unroll
                for (int j = 0; j < 4; j++) az[i][j] = sB1[tc+j];
            for (int d = 0; d < 64; d += 4) {
                float4 k4[4], w4[4];
#pragma unroll
                for (int i = 0; i < 4; i++) k4[i] = *(const float4*)&sK[(tg*4+i)*64 + d];
#pragma unroll
                for (int dd = 0; dd < 4; dd++) w4[dd] = *(const float4*)&sW1[(d+dd)*64 + tc];
#pragma unroll
                for (int i = 0; i < 4; i++) {
                    const float* kk = (const float*)&k4[i];
#pragma unroll
                    for (int dd = 0; dd < 4; dd++) {
                        const float* ww = (const float*)&w4[dd];
#pragma unroll
                        for (int j = 0; j < 4; j++) az[i][j] += kk[dd] * ww[j];
                    }
                }
            }
#pragma unroll
            for (int i = 0; i < 4; i++)
#pragma unroll
                for (int j = 0; j < 4; j++) sZ[(tg*4+i)*64 + tc + j] = az[i][j];
        }
        __syncthreads();

        for (int j = 0; j < 8; j++) {
            int n = warp + 8*j;
            float z0 = sZ[n*64 + lane], z1 = sZ[n*64 + lane + 32];
            float mu = warpsum(z0 + z1) * (1.0f/64);
            float d0 = z0 - mu, d1 = z1 - mu;
            float var = warpsum(d0*d0 + d1*d1) * (1.0f/64);
            float rstd = rsqrtf(var + 1e-6f);
            float xh0 = d0*rstd, xh1 = d1*rstd;
            float t0 = sV[n*64 + lane]      - sK[n*64 + lane];
            float t1 = sV[n*64 + lane + 32] - sK[n*64 + lane + 32];
            float g0 = sGw[lane], g1 = sGw[lane + 32];
            float gho0 = (g0*xh0 + sGb[lane]      - t0) * g0;
            float gho1 = (g1*xh1 + sGb[lane + 32] - t1) * g1;
            float sg  = warpsum(gho0 + gho1);
            float sgx = warpsum(gho0*xh0 + gho1*xh1);
            float e = sEta[n];
            float inv = rstd * (1.0f/64) * e;
            sZ[n*64 + lane]      = (64.f*gho0 - sg - xh0*sgx) * inv;
            sZ[n*64 + lane + 32] = (64.f*gho1 - sg - xh1*sgx) * inv;
        }
        __syncthreads();

        for (int n = 0; n < 64; n++) {
            float4 k4 = *(const float4*)&sK[n*64 + tg*4];
            float4 e4 = *(const float4*)&sZ[n*64 + tc];
            const float* kk = (const float*)&k4;
            const float* ee = (const float*)&e4;
#pragma unroll
            for (int i = 0; i < 4; i++)
#pragma unroll
                for (int j = 0; j < 4; j++) accW[i][j] += kk[i] * ee[j];
            if (tg == 0) {
#pragma unroll
                for (int j = 0; j < 4; j++) accB[j] += ee[j];
            }
        }
        __syncthreads();
    }

    float* dWb = dW + (size_t)bh*4096;
#pragma unroll
    for (int i = 0; i < 4; i++)
#pragma unroll
        for (int j = 0; j < 4; j++)
            atomicAdd(&dWb[(tg*4+i)*64 + tc + j], accW[i][j]);
    if (tg == 0) {
#pragma unroll
        for (int j = 0; j < 4; j++) atomicAdd(&db[(size_t)bh*64 + tc + j], accB[j]);
    }
}

// ---------------- TTT pass 2: Z = Q@W1_bar + b1_bar, LN, out; 6 blocks per (b,h) ----------------
__global__ void __launch_bounds__(256) ttt_p2(
    const __half* __restrict__ qkv,
    const float* __restrict__ W1g, const float* __restrict__ b1g,
    const float* __restrict__ tttw, const float* __restrict__ tttb,
    const float* __restrict__ dW, const float* __restrict__ db,
    __half* __restrict__ attn)
{
    extern __shared__ float sm[];
    float* sW1  = sm;            // 4096 (= W1_bar)
    float* sK   = sm + 4096;
    float* sZ   = sm + 8192;
    float* sGw  = sm + 12288;    // 64
    float* sGb  = sGw + 64;
    float* sB1b = sGb + 64;

    int bh = blockIdx.x / 6, part = blockIdx.x % 6;
    int clo = (part*16)/6, chi = ((part+1)*16)/6;
    int b = bh / NH, h = bh % NH;
    int tid = threadIdx.x;
    int lane = tid & 31, warp = tid >> 5;
    int tg = tid >> 4;
    int tc = (tid & 15) * 4;

    for (int i = tid; i < 4096; i += 256)
        sW1[i] = W1g[h*4096 + i] - dW[(size_t)bh*4096 + i];
    if (tid < 64) {
        sGw[tid] = tttw[h*64 + tid];
        sGb[tid] = tttb[h*64 + tid];
        sB1b[tid] = b1g[h*64 + tid] - db[(size_t)bh*64 + tid];
    }
    __syncthreads();

    const size_t rs = 3*CC;
    const __half* qbase = qkv + (size_t)b*NN*rs + 0*CC + h*HD;

    for (int c = clo; c < chi; c++) {
        int n0 = c * 64;
        for (int i = tid; i < 2048; i += 256) {
            int n = i >> 5, e2 = (i & 31) * 2;
            float2 qf = __half22float2(*(const __half2*)&qbase[(size_t)(n0+n)*rs + e2]);
            sK[n*64 + e2] = qf.x; sK[n*64 + e2 + 1] = qf.y;
        }
        __syncthreads();
        {
            float az[4][4];
#pragma unroll
            for (int i = 0; i < 4; i++)
#pragma unroll
                for (int j = 0; j < 4; j++) az[i][j] = sB1b[tc+j];
            for (int d = 0; d < 64; d += 4) {
                float4 k4[4], w4[4];
#pragma unroll
                for (int i = 0; i < 4; i++) k4[i] = *(const float4*)&sK[(tg*4+i)*64 + d];
#pragma unroll
                for (int dd = 0; dd < 4; dd++) w4[dd] = *(const float4*)&sW1[(d+dd)*64 + tc];
#pragma unroll
                for (int i = 0; i < 4; i++) {
                    const float* kk = (const float*)&k4[i];
#pragma unroll
                    for (int dd = 0; dd < 4; dd++) {
                        const float* ww = (const float*)&w4[dd];
#pragma unroll
                        for (int j = 0; j < 4; j++) az[i][j] += kk[dd] * ww[j];
                    }
                }
            }
#pragma unroll
            for (int i = 0; i < 4; i++)
#pragma unroll
                for (int j = 0; j < 4; j++) sZ[(tg*4+i)*64 + tc + j] = az[i][j];
        }
        __syncthreads();
        for (int j = 0; j < 8; j++) {
            int n = warp + 8*j;
            float z0 = sZ[n*64 + lane], z1 = sZ[n*64 + lane + 32];
            float mu = warpsum(z0 + z1) * (1.0f/64);
            float d0 = z0 - mu, d1 = z1 - mu;
            float var = warpsum(d0*d0 + d1*d1) * (1.0f/64);
            float rstd = rsqrtf(var + 1e-6f);
            float o0 = sK[n*64 + lane]      + sGw[lane]     *d0*rstd + sGb[lane];
            float o1 = sK[n*64 + lane + 32] + sGw[lane + 32]*d1*rstd + sGb[lane + 32];
            size_t orow = ((size_t)(b*NN + n0 + n))*CC + h*HD;
            attn[orow + lane]      = __float2half_rn(o0);
            attn[orow + lane + 32] = __float2half_rn(o1);
        }
        __syncthreads();
    }
}

// ---------------- launch ----------------
extern "C" void kernel_launch(void* const* d_in, const int* in_sizes, int n_in,
                              void* d_out, int out_size) {
    const float* x      = (const float*)d_in[0];
    const float* qkv_w  = (const float*)d_in[1];
    const float* q_bias = (const float*)d_in[2];
    const float* v_bias = (const float*)d_in[3];
    const float* proj_w = (const float*)d_in[4];
    const float* proj_b = (const float*)d_in[5];
    const float* lr_w   = (const float*)d_in[6];
    const float* lr_b   = (const float*)d_in[7];
    const float* W1     = (const float*)d_in[8];
    const float* b1     = (const float*)d_in[9];
    const float* ttt_w  = (const float*)d_in[10];
    const float* ttt_b  = (const float*)d_in[11];
    const float* n1w    = (const float*)d_in[12];
    const float* n1b    = (const float*)d_in[13];
    const float* n2w    = (const float*)d_in[14];
    const float* n2b    = (const float*)d_in[15];
    const float* fc1_w  = (const float*)d_in[16];
    const float* fc1_b  = (const float*)d_in[17];
    const float* fc2_w  = (const float*)d_in[18];
    const float* fc2_b  = (const float*)d_in[19];
    float* out = (float*)d_out;

    float *etap, *x2, *qbias, *dWp, *dbp;
    __half *qkvp, *hp, *attnp, *actp, *wq, *wp, *w1, *w2;
    cudaGetSymbolAddress((void**)&qkvp,  g_qkv);
    cudaGetSymbolAddress((void**)&etap,  g_eta);
    cudaGetSymbolAddress((void**)&x2,    g_x2);
    cudaGetSymbolAddress((void**)&qbias, g_qkvbias);
    cudaGetSymbolAddress((void**)&dWp,   g_dW);
    cudaGetSymbolAddress((void**)&dbp,   g_db);
    cudaGetSymbolAddress((void**)&hp,    g_h);
    cudaGetSymbolAddress((void**)&attnp, g_attn);
    cudaGetSymbolAddress((void**)&actp,  g_act);
    cudaGetSymbolAddress((void**)&wq,    g_wq);
    cudaGetSymbolAddress((void**)&wp,    g_wp);
    cudaGetSymbolAddress((void**)&w1,    g_w1);
    cudaGetSymbolAddress((void**)&w2,    g_w2);

    const int P1_SMEM = (16384 + 64*4) * 4;
    const int P2_SMEM = (12288 + 64*3) * 4;
    cudaFuncSetAttribute(ttt_p1, cudaFuncAttributeMaxDynamicSharedMemorySize, P1_SMEM);
    cudaFuncSetAttribute(ttt_p2, cudaFuncAttributeMaxDynamicSharedMemorySize, P2_SMEM);
    cudaFuncSetAttribute(gemm_mma<1>, cudaFuncAttributeMaxDynamicSharedMemorySize, GEMM_SMEM);
    cudaFuncSetAttribute(gemm_mma<2>, cudaFuncAttributeMaxDynamicSharedMemorySize, GEMM_SMEM);
    cudaFuncSetAttribute(gemm_mma<3>, cudaFuncAttributeMaxDynamicSharedMemorySize, GEMM_SMEM);

    const int WTOT = WQ_N + WP_N + W1_N + W2_N;
    convert_w<<<(WTOT + 255)/256, 256>>>(qkv_w, proj_w, fc1_w, fc2_w, wq, wp, w1, w2);
    qkvbias_kernel<<<(3*CC + 255)/256, 256>>>(q_bias, v_bias, qbias);
    cudaMemsetAsync(dWp, 0, (size_t)BB*NH*HD*HD*sizeof(float));
    cudaMemsetAsync(dbp, 0, (size_t)BB*NH*HD*sizeof(float));

    // LN1 + eta (warp-per-row)
    ln_kernel<<<ROWS/8, 256>>>(x, n1w, n1b, lr_w, lr_b, hp, etap);
    // qkv = h @ qkv_w^T + qkvbias  (fp16 out)
    gemm_mma<3><<<dim3(3*CC/BN, ROWS/BM), GTHREADS, GEMM_SMEM>>>(
        hp, wq, qbias, nullptr, nullptr, qkvp, ROWS, 3*CC, CC);
    // TTT pass 1 (partial dW/db) + pass 2 (output)
    ttt_p1<<<BB*NH*3, 256, P1_SMEM>>>(qkvp, etap, W1, b1, ttt_w, ttt_b, dWp, dbp);
    ttt_p2<<<BB*NH*6, 256, P2_SMEM>>>(qkvp, W1, b1, ttt_w, ttt_b, dWp, dbp, attnp);
    // x2 = x + attn @ proj_w^T + proj_b
    gemm_mma<1><<<dim3(CC/BN, ROWS/BM), GTHREADS, GEMM_SMEM>>>(
        attnp, wp, proj_b, x, x2, nullptr, ROWS, CC, CC);
    // LN2
    ln_kernel<<<ROWS/8, 256>>>(x2, n2w, n2b, nullptr, nullptr, hp, nullptr);
    // act = gelu(h2 @ fc1_w^T + fc1_b)
    gemm_mma<2><<<dim3(4*CC/BN, ROWS/BM), GTHREADS, GEMM_SMEM>>>(
        hp, w1, fc1_b, nullptr, nullptr, actp, ROWS, 4*CC, CC);
    // out = x2 + act @ fc2_w^T + fc2_b
    gemm_mma<1><<<dim3(CC/BN, ROWS/BM), GTHREADS, GEMM_SMEM>>>(
        actp, w2, fc2_b, x2, out, nullptr, ROWS, CC, 4*CC);
}

// round 15
// speedup vs baseline: 1.0995x; 1.0220x over previous
#include <cuda_runtime.h>
#include <cuda_fp16.h>
#include <math.h>
#include <stdint.h>

#define BB 16
#define NN 1024
#define CC 768
#define NH 12
#define HD 64
#define ROWS (BB*NN)        // 16384

// GEMM tiling: block 128x128, BK=64, 2-stage cp.async, 8 warps 2x4 (warp 64x32)
#define BM 128
#define BN 128
#define BK 64
#define PITCH 72
#define PLANE_EL (128*PITCH)
#define STAGE_EL (2*PLANE_EL)
#define GEMM_SMEM (2*STAGE_EL*2)             // 73728 B -> 2 CTAs/SM
#define GTHREADS 256

#define DWDB 4160                            // 4096 dW + 64 db per (b,h)

// ---------------- device scratch ----------------
__device__ float g_eta[BB*NH*NN];
__device__ float g_x2[ROWS*CC];
__device__ float g_qkvbias[3*CC];
__device__ float g_dWdb[BB*NH*DWDB];
__device__ __align__(16) __half g_qkv[ROWS*3*CC];
__device__ __align__(16) __half g_h[ROWS*CC];
__device__ __align__(16) __half g_attn[ROWS*CC];
__device__ __align__(16) __half g_act[ROWS*4*CC];
__device__ __align__(16) __half g_wq[3*CC*CC];
__device__ __align__(16) __half g_wp[CC*CC];
__device__ __align__(16) __half g_w1[4*CC*CC];
__device__ __align__(16) __half g_w2[CC*4*CC];

// ---------------- helpers ----------------
__device__ __forceinline__ float warpsum(float v) {
#pragma unroll
    for (int o = 16; o > 0; o >>= 1) v += __shfl_xor_sync(0xffffffffu, v, o);
    return v;
}
__device__ __forceinline__ void mma16816(float* d, const uint32_t* a, const uint32_t* b) {
    asm volatile(
        "mma.sync.aligned.m16n8k16.row.col.f32.f16.f16.f32 "
        "{%0,%1,%2,%3}, {%4,%5,%6,%7}, {%8,%9}, {%0,%1,%2,%3};"
        : "+f"(d[0]), "+f"(d[1]), "+f"(d[2]), "+f"(d[3])
        : "r"(a[0]), "r"(a[1]), "r"(a[2]), "r"(a[3]), "r"(b[0]), "r"(b[1]));
}
__device__ __forceinline__ void cpasync16(uint32_t dst, const void* src) {
    asm volatile("cp.async.cg.shared.global [%0], [%1], 16;" :: "r"(dst), "l"(src));
}
__device__ __forceinline__ uint32_t smaddr(const void* p) {
    uint32_t a;
    asm("{ .reg .u64 t; cvta.to.shared.u64 t, %1; cvt.u32.u64 %0, t; }" : "=r"(a) : "l"(p));
    return a;
}
__device__ __forceinline__ void ldm_x4(uint32_t* r, uint32_t addr) {
    asm volatile("ldmatrix.sync.aligned.m8n8.x4.shared.b16 {%0,%1,%2,%3}, [%4];"
        : "=r"(r[0]), "=r"(r[1]), "=r"(r[2]), "=r"(r[3]) : "r"(addr));
}

// ---------------- merged prep: weight fp32->fp16 + qkv bias build ----------------
#define WQ_N (3*CC*CC)
#define WP_N (CC*CC)
#define W1_N (4*CC*CC)
#define W2_N (CC*4*CC)
#define WTOT (WQ_N + WP_N + W1_N + W2_N)
__global__ void convert_w(const float* __restrict__ qkv_w, const float* __restrict__ proj_w,
                          const float* __restrict__ fc1_w, const float* __restrict__ fc2_w,
                          const float* __restrict__ qb, const float* __restrict__ vb,
                          __half* __restrict__ wq, __half* __restrict__ wp,
                          __half* __restrict__ w1, __half* __restrict__ w2,
                          float* __restrict__ qbias) {
    int i = blockIdx.x * blockDim.x + threadIdx.x;
    if (i < WQ_N) wq[i] = __float2half_rn(qkv_w[i]);
    else if (i < WQ_N + WP_N) { int j = i - WQ_N; wp[j] = __float2half_rn(proj_w[j]); }
    else if (i < WQ_N + WP_N + W1_N) { int j = i - WQ_N - WP_N; w1[j] = __float2half_rn(fc1_w[j]); }
    else if (i < WTOT) { int j = i - WQ_N - WP_N - W1_N; w2[j] = __float2half_rn(fc2_w[j]); }
    else if (i < WTOT + 3*CC) {
        int j = i - WTOT;
        qbias[j] = (j < CC) ? qb[j] : (j < 2*CC ? 0.0f : vb[j - 2*CC]);
    }
}

// ---------------- LayerNorm, warp-per-row (+ optional eta), fp16 out ----------------
__global__ void __launch_bounds__(256) ln_kernel(
    const float* __restrict__ x, const float* __restrict__ w, const float* __restrict__ bp,
    const float* __restrict__ lrw, const float* __restrict__ lrb,
    __half* __restrict__ hout, float* __restrict__ eta)
{
    int lane = threadIdx.x & 31, warp = threadIdx.x >> 5;
    int row = blockIdx.x * 8 + warp;
    const float4* xr = (const float4*)(x + (size_t)row * CC);

    float4 v[6];
    float s = 0.f;
#pragma unroll
    for (int j = 0; j < 6; j++) {
        v[j] = xr[j*32 + lane];
        s += v[j].x + v[j].y + v[j].z + v[j].w;
    }
    float mu = warpsum(s) * (1.0f/CC);
    float vs = 0.f;
#pragma unroll
    for (int j = 0; j < 6; j++) {
        v[j].x -= mu; v[j].y -= mu; v[j].z -= mu; v[j].w -= mu;
        vs += v[j].x*v[j].x + v[j].y*v[j].y + v[j].z*v[j].z + v[j].w*v[j].w;
    }
    float rstd = rsqrtf(warpsum(vs) * (1.0f/CC) + 1e-6f);

    const float4* wv = (const float4*)w;
    const float4* bv = (const float4*)bp;
    float h[24];
#pragma unroll
    for (int j = 0; j < 6; j++) {
        float4 ww = wv[j*32 + lane], bb = bv[j*32 + lane];
        h[j*4+0] = ww.x * v[j].x * rstd + bb.x;
        h[j*4+1] = ww.y * v[j].y * rstd + bb.y;
        h[j*4+2] = ww.z * v[j].z * rstd + bb.z;
        h[j*4+3] = ww.w * v[j].w * rstd + bb.w;
    }
    __half* hr = hout + (size_t)row * CC;
#pragma unroll
    for (int j = 0; j < 6; j++) {
        __half2 a = __floats2half2_rn(h[j*4+0], h[j*4+1]);
        __half2 b = __floats2half2_rn(h[j*4+2], h[j*4+3]);
        *(uint2*)&hr[(j*32 + lane)*4] = make_uint2(*(uint32_t*)&a, *(uint32_t*)&b);
    }

    if (eta) {
#pragma unroll
        for (int hh = 0; hh < NH; hh++) {
            const float4* lw = (const float4*)(lrw + (size_t)hh * CC);
            float p = 0.f;
#pragma unroll
            for (int j = 0; j < 6; j++) {
                float4 l4 = lw[j*32 + lane];
                p += h[j*4+0]*l4.x + h[j*4+1]*l4.y + h[j*4+2]*l4.z + h[j*4+3]*l4.w;
            }
            p = warpsum(p);
            if (lane == hh) {
                p += lrb[hh];
                float sg = 1.0f / (1.0f + expf(-p));
                int b = row >> 10, n = row & 1023;
                eta[((size_t)(b*NH + hh))*NN + n] = sg * (1.0f/HD);
            }
        }
    }
}

// ---------------- cp.async + ldmatrix 2-stage BK=64 fp16 GEMM NT ----------------
// EPI: 0 = fp32 out; 1 = +Res fp32 out; 2 = gelu fp16 out; 3 = plain fp16 out
template<int EPI>
__global__ void __launch_bounds__(GTHREADS, 2) gemm_mma(
    const __half* __restrict__ A, const __half* __restrict__ Bw,
    const float* __restrict__ bias, const float* __restrict__ Res,
    float* __restrict__ Cout, __half* __restrict__ Ch,
    int M, int Nn, int K)
{
    extern __shared__ __half smem[];
    uint32_t smbase = smaddr(smem);

    int tid = threadIdx.x;
    int lane = tid & 31, wid = tid >> 5;
    int wm = wid & 1, wn = wid >> 1;
    int g = lane >> 2, t4 = lane & 3;
    int bn = blockIdx.x * BN, bm = blockIdx.y * BM;
    const int nch = K / BK;

    const __half* Ag = A  + (size_t)bm*K;
    const __half* Bg = Bw + (size_t)bn*K;

    int aRow = (wm*64 + (lane & 15))*PITCH + (lane >> 4)*8;
    int bRow = (wn*32 + (lane >> 4)*8 + (lane & 7))*PITCH + ((lane >> 3) & 1)*8;

    float acc[4][4][4];
#pragma unroll
    for (int i = 0; i < 4; i++)
#pragma unroll
        for (int j = 0; j < 4; j++)
#pragma unroll
            for (int k = 0; k < 4; k++) acc[i][j][k] = 0.f;

#define ISSUE(stage, c) do {                                                    \
        int kb = (c) * BK;                                                      \
        uint32_t sb = smbase + ((stage)*STAGE_EL)*2;                            \
        _Pragma("unroll")                                                       \
        for (int it = 0; it < 4; it++) {                                        \
            int u = tid + it*256;                                               \
            int r0_ = u >> 3, s0_ = u & 7;                                      \
            cpasync16(sb + (r0_*PITCH + s0_*8)*2,                               \
                      Ag + (size_t)r0_*K + kb + s0_*8);                         \
            cpasync16(sb + (PLANE_EL + r0_*PITCH + s0_*8)*2,                    \
                      Bg + (size_t)r0_*K + kb + s0_*8);                         \
        }                                                                       \
        asm volatile("cp.async.commit_group;" ::: "memory");                    \
    } while (0)

    ISSUE(0, 0);

    for (int c = 0; c < nch; ++c) {
        int s = c & 1;
        asm volatile("cp.async.wait_group 0;" ::: "memory");
        __syncthreads();
        if (c + 1 < nch) ISSUE(s ^ 1, c + 1);

        uint32_t pA = smbase + (s*STAGE_EL)*2;
        uint32_t pB = smbase + (s*STAGE_EL + PLANE_EL)*2;

#pragma unroll
        for (int ks = 0; ks < 4; ks++) {
            int kof = ks*16;
            uint32_t ah[4][4], bh[4][2];
#pragma unroll
            for (int mb = 0; mb < 4; mb++)
                ldm_x4(ah[mb], pA + (aRow + mb*16*PITCH + kof)*2);
#pragma unroll
            for (int p = 0; p < 2; p++) {
                uint32_t r[4];
                ldm_x4(r, pB + (bRow + p*16*PITCH + kof)*2);
                bh[2*p][0] = r[0]; bh[2*p][1] = r[1]; bh[2*p+1][0] = r[2]; bh[2*p+1][1] = r[3];
            }
#pragma unroll
            for (int mt = 0; mt < 4; mt++)
#pragma unroll
                for (int nt = 0; nt < 4; nt++) mma16816(acc[mt][nt], ah[mt], bh[nt]);
        }
    }
#undef ISSUE

#pragma unroll
    for (int mt = 0; mt < 4; mt++) {
#pragma unroll
        for (int nt = 0; nt < 4; nt++) {
            int r0 = bm + wm*64 + mt*16 + g;
            int c0 = bn + wn*32 + nt*8 + t4*2;
            float b0 = bias[c0], b1 = bias[c0+1];
#pragma unroll
            for (int half = 0; half < 2; half++) {
                int r = r0 + half*8;
                size_t gi = (size_t)r * Nn + c0;
                float v0 = acc[mt][nt][half*2]     + b0;
                float v1 = acc[mt][nt][half*2 + 1] + b1;
                if (EPI == 1) { v0 += Res[gi]; v1 += Res[gi+1]; }
                if (EPI == 2) {
                    v0 = 0.5f*v0*(1.0f + erff(v0*0.70710678118654752f));
                    v1 = 0.5f*v1*(1.0f + erff(v1*0.70710678118654752f));
                }
                if (EPI == 2 || EPI == 3) {
                    __half2 hv = __floats2half2_rn(v0, v1);
                    *(uint32_t*)&Ch[gi] = *(uint32_t*)&hv;
                } else {
                    Cout[gi]   = v0;
                    Cout[gi+1] = v1;
                }
            }
        }
    }
}

// ---------------- TTT pass 1: partial dW/db, 4 blocks per (b,h) ----------------
__global__ void __launch_bounds__(256) ttt_p1(
    const __half* __restrict__ qkv, const float* __restrict__ eta,
    const float* __restrict__ W1g, const float* __restrict__ b1g,
    const float* __restrict__ tttw, const float* __restrict__ tttb,
    float* __restrict__ dWdb)
{
    extern __shared__ float sm[];
    float* sW1  = sm;            // 4096
    float* sK   = sm + 4096;
    float* sV   = sm + 8192;
    float* sZ   = sm + 12288;
    float* sEta = sm + 16384;    // 64
    float* sGw  = sEta + 64;
    float* sGb  = sGw + 64;
    float* sB1  = sGb + 64;

    int bh = blockIdx.x >> 2, part = blockIdx.x & 3;
    int clo = part*4, chi = clo + 4;
    int b = bh / NH, h = bh % NH;
    int tid = threadIdx.x;
    int lane = tid & 31, warp = tid >> 5;
    int tg = tid >> 4;
    int tc = (tid & 15) * 4;

    for (int i = tid; i < 4096; i += 256) sW1[i] = W1g[h*4096 + i];
    if (tid < 64) {
        sGw[tid] = tttw[h*64 + tid];
        sGb[tid] = tttb[h*64 + tid];
        sB1[tid] = b1g[h*64 + tid];
    }
    __syncthreads();

    const size_t rs = 3*CC;
    const __half* kbase = qkv + (size_t)b*NN*rs + 1*CC + h*HD;
    const __half* vbase = qkv + (size_t)b*NN*rs + 2*CC + h*HD;

    float accW[4][4];
#pragma unroll
    for (int i = 0; i < 4; i++)
#pragma unroll
        for (int j = 0; j < 4; j++) accW[i][j] = 0.f;
    float accB[4] = {0.f, 0.f, 0.f, 0.f};

    for (int c = clo; c < chi; c++) {
        int n0 = c * 64;
        for (int i = tid; i < 2048; i += 256) {
            int n = i >> 5, e2 = (i & 31) * 2;
            float2 kf = __half22float2(*(const __half2*)&kbase[(size_t)(n0+n)*rs + e2]);
            float2 vf = __half22float2(*(const __half2*)&vbase[(size_t)(n0+n)*rs + e2]);
            sK[n*64 + e2] = kf.x; sK[n*64 + e2 + 1] = kf.y;
            sV[n*64 + e2] = vf.x; sV[n*64 + e2 + 1] = vf.y;
        }
        if (tid < 64) sEta[tid] = eta[(size_t)bh*NN + n0 + tid];
        __syncthreads();

        {
            float az[4][4];
#pragma unroll
            for (int i = 0; i < 4; i++)
#pragma unroll
                for (int j = 0; j < 4; j++) az[i][j] = sB1[tc+j];
            for (int d = 0; d < 64; d += 4) {
                float4 k4[4], w4[4];
#pragma unroll
                for (int i = 0; i < 4; i++) k4[i] = *(const float4*)&sK[(tg*4+i)*64 + d];
#pragma unroll
                for (int dd = 0; dd < 4; dd++) w4[dd] = *(const float4*)&sW1[(d+dd)*64 + tc];
#pragma unroll
                for (int i = 0; i < 4; i++) {
                    const float* kk = (const float*)&k4[i];
#pragma unroll
                    for (int dd = 0; dd < 4; dd++) {
                        const float* ww = (const float*)&w4[dd];
#pragma unroll
                        for (int j = 0; j < 4; j++) az[i][j] += kk[dd] * ww[j];
                    }
                }
            }
#pragma unroll
            for (int i = 0; i < 4; i++)
#pragma unroll
                for (int j = 0; j < 4; j++) sZ[(tg*4+i)*64 + tc + j] = az[i][j];
        }
        __syncthreads();

        for (int j = 0; j < 8; j++) {
            int n = warp + 8*j;
            float z0 = sZ[n*64 + lane], z1 = sZ[n*64 + lane + 32];
            float mu = warpsum(z0 + z1) * (1.0f/64);
            float d0 = z0 - mu, d1 = z1 - mu;
            float var = warpsum(d0*d0 + d1*d1) * (1.0f/64);
            float rstd = rsqrtf(var + 1e-6f);
            float xh0 = d0*rstd, xh1 = d1*rstd;
            float t0 = sV[n*64 + lane]      - sK[n*64 + lane];
            float t1 = sV[n*64 + lane + 32] - sK[n*64 + lane + 32];
            float g0 = sGw[lane], g1 = sGw[lane + 32];
            float gho0 = (g0*xh0 + sGb[lane]      - t0) * g0;
            float gho1 = (g1*xh1 + sGb[lane + 32] - t1) * g1;
            float sg  = warpsum(gho0 + gho1);
            float sgx = warpsum(gho0*xh0 + gho1*xh1);
            float e = sEta[n];
            float inv = rstd * (1.0f/64) * e;
            sZ[n*64 + lane]      = (64.f*gho0 - sg - xh0*sgx) * inv;
            sZ[n*64 + lane + 32] = (64.f*gho1 - sg - xh1*sgx) * inv;
        }
        __syncthreads();

        for (int n = 0; n < 64; n++) {
            float4 k4 = *(const float4*)&sK[n*64 + tg*4];
            float4 e4 = *(const float4*)&sZ[n*64 + tc];
            const float* kk = (const float*)&k4;
            const float* ee = (const float*)&e4;
#pragma unroll
            for (int i = 0; i < 4; i++)
#pragma unroll
                for (int j = 0; j < 4; j++) accW[i][j] += kk[i] * ee[j];
            if (tg == 0) {
#pragma unroll
                for (int j = 0; j < 4; j++) accB[j] += ee[j];
            }
        }
        __syncthreads();
    }

    float* base = dWdb + (size_t)bh*DWDB;
#pragma unroll
    for (int i = 0; i < 4; i++)
#pragma unroll
        for (int j = 0; j < 4; j++)
            atomicAdd(&base[(tg*4+i)*64 + tc + j], accW[i][j]);
    if (tg == 0) {
#pragma unroll
        for (int j = 0; j < 4; j++) atomicAdd(&base[4096 + tc + j], accB[j]);
    }
}

// ---------------- TTT pass 2: Z = Q@W1_bar + b1_bar, LN, out; 8 blocks per (b,h) ----------------
__global__ void __launch_bounds__(256) ttt_p2(
    const __half* __restrict__ qkv,
    const float* __restrict__ W1g, const float* __restrict__ b1g,
    const float* __restrict__ tttw, const float* __restrict__ tttb,
    const float* __restrict__ dWdb,
    __half* __restrict__ attn)
{
    extern __shared__ float sm[];
    float* sW1  = sm;            // 4096 (= W1_bar)
    float* sK   = sm + 4096;
    float* sZ   = sm + 8192;
    float* sGw  = sm + 12288;    // 64
    float* sGb  = sGw + 64;
    float* sB1b = sGb + 64;

    int bh = blockIdx.x >> 3, part = blockIdx.x & 7;
    int clo = part*2, chi = clo + 2;
    int b = bh / NH, h = bh % NH;
    int tid = threadIdx.x;
    int lane = tid & 31, warp = tid >> 5;
    int tg = tid >> 4;
    int tc = (tid & 15) * 4;

    const float* base = dWdb + (size_t)bh*DWDB;
    for (int i = tid; i < 4096; i += 256)
        sW1[i] = W1g[h*4096 + i] - base[i];
    if (tid < 64) {
        sGw[tid] = tttw[h*64 + tid];
        sGb[tid] = tttb[h*64 + tid];
        sB1b[tid] = b1g[h*64 + tid] - base[4096 + tid];
    }
    __syncthreads();

    const size_t rs = 3*CC;
    const __half* qbase = qkv + (size_t)b*NN*rs + 0*CC + h*HD;

    for (int c = clo; c < chi; c++) {
        int n0 = c * 64;
        for (int i = tid; i < 2048; i += 256) {
            int n = i >> 5, e2 = (i & 31) * 2;
            float2 qf = __half22float2(*(const __half2*)&qbase[(size_t)(n0+n)*rs + e2]);
            sK[n*64 + e2] = qf.x; sK[n*64 + e2 + 1] = qf.y;
        }
        __syncthreads();
        {
            float az[4][4];
#pragma unroll
            for (int i = 0; i < 4; i++)
#pragma unroll
                for (int j = 0; j < 4; j++) az[i][j] = sB1b[tc+j];
            for (int d = 0; d < 64; d += 4) {
                float4 k4[4], w4[4];
#pragma unroll
                for (int i = 0; i < 4; i++) k4[i] = *(const float4*)&sK[(tg*4+i)*64 + d];
#pragma unroll
                for (int dd = 0; dd < 4; dd++) w4[dd] = *(const float4*)&sW1[(d+dd)*64 + tc];
#pragma unroll
                for (int i = 0; i < 4; i++) {
                    const float* kk = (const float*)&k4[i];
#pragma unroll
                    for (int dd = 0; dd < 4; dd++) {
                        const float* ww = (const float*)&w4[dd];
#pragma unroll
                        for (int j = 0; j < 4; j++) az[i][j] += kk[dd] * ww[j];
                    }
                }
            }
#pragma unroll
            for (int i = 0; i < 4; i++)
#pragma unroll
                for (int j = 0; j < 4; j++) sZ[(tg*4+i)*64 + tc + j] = az[i][j];
        }
        __syncthreads();
        for (int j = 0; j < 8; j++) {
            int n = warp + 8*j;
            float z0 = sZ[n*64 + lane], z1 = sZ[n*64 + lane + 32];
            float mu = warpsum(z0 + z1) * (1.0f/64);
            float d0 = z0 - mu, d1 = z1 - mu;
            float var = warpsum(d0*d0 + d1*d1) * (1.0f/64);
            float rstd = rsqrtf(var + 1e-6f);
            float o0 = sK[n*64 + lane]      + sGw[lane]     *d0*rstd + sGb[lane];
            float o1 = sK[n*64 + lane + 32] + sGw[lane + 32]*d1*rstd + sGb[lane + 32];
            size_t orow = ((size_t)(b*NN + n0 + n))*CC + h*HD;
            attn[orow + lane]      = __float2half_rn(o0);
            attn[orow + lane + 32] = __float2half_rn(o1);
        }
        __syncthreads();
    }
}

// ---------------- launch ----------------
extern "C" void kernel_launch(void* const* d_in, const int* in_sizes, int n_in,
                              void* d_out, int out_size) {
    const float* x      = (const float*)d_in[0];
    const float* qkv_w  = (const float*)d_in[1];
    const float* q_bias = (const float*)d_in[2];
    const float* v_bias = (const float*)d_in[3];
    const float* proj_w = (const float*)d_in[4];
    const float* proj_b = (const float*)d_in[5];
    const float* lr_w   = (const float*)d_in[6];
    const float* lr_b   = (const float*)d_in[7];
    const float* W1     = (const float*)d_in[8];
    const float* b1     = (const float*)d_in[9];
    const float* ttt_w  = (const float*)d_in[10];
    const float* ttt_b  = (const float*)d_in[11];
    const float* n1w    = (const float*)d_in[12];
    const float* n1b    = (const float*)d_in[13];
    const float* n2w    = (const float*)d_in[14];
    const float* n2b    = (const float*)d_in[15];
    const float* fc1_w  = (const float*)d_in[16];
    const float* fc1_b  = (const float*)d_in[17];
    const float* fc2_w  = (const float*)d_in[18];
    const float* fc2_b  = (const float*)d_in[19];
    float* out = (float*)d_out;

    float *etap, *x2, *qbias, *dWdbp;
    __half *qkvp, *hp, *attnp, *actp, *wq, *wp, *w1, *w2;
    cudaGetSymbolAddress((void**)&qkvp,  g_qkv);
    cudaGetSymbolAddress((void**)&etap,  g_eta);
    cudaGetSymbolAddress((void**)&x2,    g_x2);
    cudaGetSymbolAddress((void**)&qbias, g_qkvbias);
    cudaGetSymbolAddress((void**)&dWdbp, g_dWdb);
    cudaGetSymbolAddress((void**)&hp,    g_h);
    cudaGetSymbolAddress((void**)&attnp, g_attn);
    cudaGetSymbolAddress((void**)&actp,  g_act);
    cudaGetSymbolAddress((void**)&wq,    g_wq);
    cudaGetSymbolAddress((void**)&wp,    g_wp);
    cudaGetSymbolAddress((void**)&w1,    g_w1);
    cudaGetSymbolAddress((void**)&w2,    g_w2);

    const int P1_SMEM = (16384 + 64*4) * 4;
    const int P2_SMEM = (12288 + 64*3) * 4;
    cudaFuncSetAttribute(ttt_p1, cudaFuncAttributeMaxDynamicSharedMemorySize, P1_SMEM);
    cudaFuncSetAttribute(ttt_p2, cudaFuncAttributeMaxDynamicSharedMemorySize, P2_SMEM);
    cudaFuncSetAttribute(gemm_mma<1>, cudaFuncAttributeMaxDynamicSharedMemorySize, GEMM_SMEM);
    cudaFuncSetAttribute(gemm_mma<2>, cudaFuncAttributeMaxDynamicSharedMemorySize, GEMM_SMEM);
    cudaFuncSetAttribute(gemm_mma<3>, cudaFuncAttributeMaxDynamicSharedMemorySize, GEMM_SMEM);

    convert_w<<<(WTOT + 3*CC + 255)/256, 256>>>(
        qkv_w, proj_w, fc1_w, fc2_w, q_bias, v_bias, wq, wp, w1, w2, qbias);
    cudaMemsetAsync(dWdbp, 0, (size_t)BB*NH*DWDB*sizeof(float));

    // LN1 + eta (warp-per-row)
    ln_kernel<<<ROWS/8, 256>>>(x, n1w, n1b, lr_w, lr_b, hp, etap);
    // qkv = h @ qkv_w^T + qkvbias  (fp16 out)
    gemm_mma<3><<<dim3(3*CC/BN, ROWS/BM), GTHREADS, GEMM_SMEM>>>(
        hp, wq, qbias, nullptr, nullptr, qkvp, ROWS, 3*CC, CC);
    // TTT pass 1 (partial dW/db) + pass 2 (output)
    ttt_p1<<<BB*NH*4, 256, P1_SMEM>>>(qkvp, etap, W1, b1, ttt_w, ttt_b, dWdbp);
    ttt_p2<<<BB*NH*8, 256, P2_SMEM>>>(qkvp, W1, b1, ttt_w, ttt_b, dWdbp, attnp);
    // x2 = x + attn @ proj_w^T + proj_b
    gemm_mma<1><<<dim3(CC/BN, ROWS/BM), GTHREADS, GEMM_SMEM>>>(
        attnp, wp, proj_b, x, x2, nullptr, ROWS, CC, CC);
    // LN2
    ln_kernel<<<ROWS/8, 256>>>(x2, n2w, n2b, nullptr, nullptr, hp, nullptr);
    // act = gelu(h2 @ fc1_w^T + fc1_b)
    gemm_mma<2><<<dim3(4*CC/BN, ROWS/BM), GTHREADS, GEMM_SMEM>>>(
        hp, w1, fc1_b, nullptr, nullptr, actp, ROWS, 4*CC, CC);
    // out = x2 + act @ fc2_w^T + fc2_b
    gemm_mma<1><<<dim3(CC/BN, ROWS/BM), GTHREADS, GEMM_SMEM>>>(
        actp, w2, fc2_b, x2, out, nullptr, ROWS, CC, 4*CC);
}

// round 17
// speedup vs baseline: 1.1429x; 1.0395x over previous
#include <cuda_runtime.h>
#include <cuda_fp16.h>
#include <math.h>
#include <stdint.h>

#define BB 16
#define NN 1024
#define CC 768
#define NH 12
#define HD 64
#define ROWS (BB*NN)        // 16384

// GEMM tiling: block 128x128, BK=64, 2-stage cp.async, 8 warps 2x4 (warp 64x32)
#define BM 128
#define BN 128
#define BK 64
#define PITCH 72
#define PLANE_EL (128*PITCH)
#define STAGE_EL (2*PLANE_EL)
#define GEMM_SMEM (2*STAGE_EL*2)             // 73728 B -> 2 CTAs/SM
#define GTHREADS 256

#define DWDB 4160                            // 4096 dW + 64 db per (b,h)
#define TP 72                                // TTT smem pitch (halves)
#define HPLANES_F 4608                       // float offset after two 64xTP half planes

// ---------------- device scratch ----------------
__device__ float g_eta[BB*NH*NN];
__device__ float g_x2[ROWS*CC];
__device__ float g_qkvbias[3*CC];
__device__ float g_dWdb[BB*NH*DWDB];
__device__ __align__(16) __half g_w1bt[BB*NH*64*TP];   // W1_bar^T fp16 per (b,h)
__device__ __align__(16) __half g_qkv[ROWS*3*CC];
__device__ __align__(16) __half g_h[ROWS*CC];
__device__ __align__(16) __half g_attn[ROWS*CC];
__device__ __align__(16) __half g_act[ROWS*4*CC];
__device__ __align__(16) __half g_wq[3*CC*CC];
__device__ __align__(16) __half g_wp[CC*CC];
__device__ __align__(16) __half g_w1[4*CC*CC];
__device__ __align__(16) __half g_w2[CC*4*CC];

// ---------------- helpers ----------------
__device__ __forceinline__ float warpsum(float v) {
#pragma unroll
    for (int o = 16; o > 0; o >>= 1) v += __shfl_xor_sync(0xffffffffu, v, o);
    return v;
}
__device__ __forceinline__ void mma16816(float* d, const uint32_t* a, const uint32_t* b) {
    asm volatile(
        "mma.sync.aligned.m16n8k16.row.col.f32.f16.f16.f32 "
        "{%0,%1,%2,%3}, {%4,%5,%6,%7}, {%8,%9}, {%0,%1,%2,%3};"
        : "+f"(d[0]), "+f"(d[1]), "+f"(d[2]), "+f"(d[3])
        : "r"(a[0]), "r"(a[1]), "r"(a[2]), "r"(a[3]), "r"(b[0]), "r"(b[1]));
}
__device__ __forceinline__ void cpasync16(uint32_t dst, const void* src) {
    asm volatile("cp.async.cg.shared.global [%0], [%1], 16;" :: "r"(dst), "l"(src));
}
__device__ __forceinline__ uint32_t smaddr(const void* p) {
    uint32_t a;
    asm("{ .reg .u64 t; cvta.to.shared.u64 t, %1; cvt.u32.u64 %0, t; }" : "=r"(a) : "l"(p));
    return a;
}
__device__ __forceinline__ void ldm_x4(uint32_t* r, uint32_t addr) {
    asm volatile("ldmatrix.sync.aligned.m8n8.x4.shared.b16 {%0,%1,%2,%3}, [%4];"
        : "=r"(r[0]), "=r"(r[1]), "=r"(r[2]), "=r"(r[3]) : "r"(addr));
}

// ---------------- merged prep: weight fp32->fp16 + qkv bias build ----------------
#define WQ_N (3*CC*CC)
#define WP_N (CC*CC)
#define W1_N (4*CC*CC)
#define W2_N (CC*4*CC)
#define WTOT (WQ_N + WP_N + W1_N + W2_N)
__global__ void convert_w(const float* __restrict__ qkv_w, const float* __restrict__ proj_w,
                          const float* __restrict__ fc1_w, const float* __restrict__ fc2_w,
                          const float* __restrict__ qb, const float* __restrict__ vb,
                          __half* __restrict__ wq, __half* __restrict__ wp,
                          __half* __restrict__ w1, __half* __restrict__ w2,
                          float* __restrict__ qbias) {
    int i = blockIdx.x * blockDim.x + threadIdx.x;
    if (i < WQ_N) wq[i] = __float2half_rn(qkv_w[i]);
    else if (i < WQ_N + WP_N) { int j = i - WQ_N; wp[j] = __float2half_rn(proj_w[j]); }
    else if (i < WQ_N + WP_N + W1_N) { int j = i - WQ_N - WP_N; w1[j] = __float2half_rn(fc1_w[j]); }
    else if (i < WTOT) { int j = i - WQ_N - WP_N - W1_N; w2[j] = __float2half_rn(fc2_w[j]); }
    else if (i < WTOT + 3*CC) {
        int j = i - WTOT;
        qbias[j] = (j < CC) ? qb[j] : (j < 2*CC ? 0.0f : vb[j - 2*CC]);
    }
}

// ---------------- LayerNorm, warp-per-row (+ optional eta), fp16 out ----------------
__global__ void __launch_bounds__(256) ln_kernel(
    const float* __restrict__ x, const float* __restrict__ w, const float* __restrict__ bp,
    const float* __restrict__ lrw, const float* __restrict__ lrb,
    __half* __restrict__ hout, float* __restrict__ eta)
{
    int lane = threadIdx.x & 31, warp = threadIdx.x >> 5;
    int row = blockIdx.x * 8 + warp;
    const float4* xr = (const float4*)(x + (size_t)row * CC);

    float4 v[6];
    float s = 0.f;
#pragma unroll
    for (int j = 0; j < 6; j++) {
        v[j] = xr[j*32 + lane];
        s += v[j].x + v[j].y + v[j].z + v[j].w;
    }
    float mu = warpsum(s) * (1.0f/CC);
    float vs = 0.f;
#pragma unroll
    for (int j = 0; j < 6; j++) {
        v[j].x -= mu; v[j].y -= mu; v[j].z -= mu; v[j].w -= mu;
        vs += v[j].x*v[j].x + v[j].y*v[j].y + v[j].z*v[j].z + v[j].w*v[j].w;
    }
    float rstd = rsqrtf(warpsum(vs) * (1.0f/CC) + 1e-6f);

    const float4* wv = (const float4*)w;
    const float4* bv = (const float4*)bp;
    float h[24];
#pragma unroll
    for (int j = 0; j < 6; j++) {
        float4 ww = wv[j*32 + lane], bb = bv[j*32 + lane];
        h[j*4+0] = ww.x * v[j].x * rstd + bb.x;
        h[j*4+1] = ww.y * v[j].y * rstd + bb.y;
        h[j*4+2] = ww.z * v[j].z * rstd + bb.z;
        h[j*4+3] = ww.w * v[j].w * rstd + bb.w;
    }
    __half* hr = hout + (size_t)row * CC;
#pragma unroll
    for (int j = 0; j < 6; j++) {
        __half2 a = __floats2half2_rn(h[j*4+0], h[j*4+1]);
        __half2 b = __floats2half2_rn(h[j*4+2], h[j*4+3]);
        *(uint2*)&hr[(j*32 + lane)*4] = make_uint2(*(uint32_t*)&a, *(uint32_t*)&b);
    }

    if (eta) {
#pragma unroll
        for (int hh = 0; hh < NH; hh++) {
            const float4* lw = (const float4*)(lrw + (size_t)hh * CC);
            float p = 0.f;
#pragma unroll
            for (int j = 0; j < 6; j++) {
                float4 l4 = lw[j*32 + lane];
                p += h[j*4+0]*l4.x + h[j*4+1]*l4.y + h[j*4+2]*l4.z + h[j*4+3]*l4.w;
            }
            p = warpsum(p);
            if (lane == hh) {
                p += lrb[hh];
                float sg = 1.0f / (1.0f + expf(-p));
                int b = row >> 10, n = row & 1023;
                eta[((size_t)(b*NH + hh))*NN + n] = sg * (1.0f/HD);
            }
        }
    }
}

// ---------------- cp.async + ldmatrix 2-stage BK=64 fp16 GEMM NT ----------------
// EPI: 0 = fp32 out; 1 = +Res fp32 out; 2 = gelu fp16 out; 3 = plain fp16 out
template<int EPI>
__global__ void __launch_bounds__(GTHREADS, 2) gemm_mma(
    const __half* __restrict__ A, const __half* __restrict__ Bw,
    const float* __restrict__ bias, const float* __restrict__ Res,
    float* __restrict__ Cout, __half* __restrict__ Ch,
    int M, int Nn, int K)
{
    extern __shared__ __half smem[];
    uint32_t smbase = smaddr(smem);

    int tid = threadIdx.x;
    int lane = tid & 31, wid = tid >> 5;
    int wm = wid & 1, wn = wid >> 1;
    int g = lane >> 2, t4 = lane & 3;
    int bn = blockIdx.x * BN, bm = blockIdx.y * BM;
    const int nch = K / BK;

    const __half* Ag = A  + (size_t)bm*K;
    const __half* Bg = Bw + (size_t)bn*K;

    int aRow = (wm*64 + (lane & 15))*PITCH + (lane >> 4)*8;
    int bRow = (wn*32 + (lane >> 4)*8 + (lane & 7))*PITCH + ((lane >> 3) & 1)*8;

    float acc[4][4][4];
#pragma unroll
    for (int i = 0; i < 4; i++)
#pragma unroll
        for (int j = 0; j < 4; j++)
#pragma unroll
            for (int k = 0; k < 4; k++) acc[i][j][k] = 0.f;

#define ISSUE(stage, c) do {                                                    \
        int kb = (c) * BK;                                                      \
        uint32_t sb = smbase + ((stage)*STAGE_EL)*2;                            \
        _Pragma("unroll")                                                       \
        for (int it = 0; it < 4; it++) {                                        \
            int u = tid + it*256;                                               \
            int r0_ = u >> 3, s0_ = u & 7;                                      \
            cpasync16(sb + (r0_*PITCH + s0_*8)*2,                               \
                      Ag + (size_t)r0_*K + kb + s0_*8);                         \
            cpasync16(sb + (PLANE_EL + r0_*PITCH + s0_*8)*2,                    \
                      Bg + (size_t)r0_*K + kb + s0_*8);                         \
        }                                                                       \
        asm volatile("cp.async.commit_group;" ::: "memory");                    \
    } while (0)

    ISSUE(0, 0);

    for (int c = 0; c < nch; ++c) {
        int s = c & 1;
        asm volatile("cp.async.wait_group 0;" ::: "memory");
        __syncthreads();
        if (c + 1 < nch) ISSUE(s ^ 1, c + 1);

        uint32_t pA = smbase + (s*STAGE_EL)*2;
        uint32_t pB = smbase + (s*STAGE_EL + PLANE_EL)*2;

#pragma unroll
        for (int ks = 0; ks < 4; ks++) {
            int kof = ks*16;
            uint32_t ah[4][4], bh[4][2];
#pragma unroll
            for (int mb = 0; mb < 4; mb++)
                ldm_x4(ah[mb], pA + (aRow + mb*16*PITCH + kof)*2);
#pragma unroll
            for (int p = 0; p < 2; p++) {
                uint32_t r[4];
                ldm_x4(r, pB + (bRow + p*16*PITCH + kof)*2);
                bh[2*p][0] = r[0]; bh[2*p][1] = r[1]; bh[2*p+1][0] = r[2]; bh[2*p+1][1] = r[3];
            }
#pragma unroll
            for (int mt = 0; mt < 4; mt++)
#pragma unroll
                for (int nt = 0; nt < 4; nt++) mma16816(acc[mt][nt], ah[mt], bh[nt]);
        }
    }
#undef ISSUE

#pragma unroll
    for (int mt = 0; mt < 4; mt++) {
#pragma unroll
        for (int nt = 0; nt < 4; nt++) {
            int r0 = bm + wm*64 + mt*16 + g;
            int c0 = bn + wn*32 + nt*8 + t4*2;
            float b0 = bias[c0], b1 = bias[c0+1];
#pragma unroll
            for (int half = 0; half < 2; half++) {
                int r = r0 + half*8;
                size_t gi = (size_t)r * Nn + c0;
                float v0 = acc[mt][nt][half*2]     + b0;
                float v1 = acc[mt][nt][half*2 + 1] + b1;
                if (EPI == 1) { v0 += Res[gi]; v1 += Res[gi+1]; }
                if (EPI == 2) {
                    v0 = 0.5f*v0*(1.0f + erff(v0*0.70710678118654752f));
                    v1 = 0.5f*v1*(1.0f + erff(v1*0.70710678118654752f));
                }
                if (EPI == 2 || EPI == 3) {
                    __half2 hv = __floats2half2_rn(v0, v1);
                    *(uint32_t*)&Ch[gi] = *(uint32_t*)&hv;
                } else {
                    Cout[gi]   = v0;
                    Cout[gi+1] = v1;
                }
            }
        }
    }
}

// ---------------- TTT pass 1: mma Z1 + fp32 LN-bwd + fp32 accW; 4 blocks per (b,h) ----------------
__global__ void __launch_bounds__(256) ttt_p1(
    const __half* __restrict__ qkv, const float* __restrict__ eta,
    const float* __restrict__ W1g, const float* __restrict__ b1g,
    const float* __restrict__ tttw, const float* __restrict__ tttb,
    float* __restrict__ dWdb)
{
    extern __shared__ float sm[];
    __half* sW1t = (__half*)sm;              // 64 x TP halves (W1^T fp16), 2304 floats
    __half* sK16 = (__half*)(sm + 2304);     // 64 x TP halves, 2304 floats
    float* sKf  = sm + HPLANES_F;            // 4096
    float* sV   = sKf + 4096;
    float* sZ   = sV + 4096;
    float* sEta = sZ + 4096;                 // 64
    float* sGw  = sEta + 64;
    float* sGb  = sGw + 64;
    float* sB1  = sGb + 64;

    int bh = blockIdx.x >> 2, part = blockIdx.x & 3;
    int clo = part*4, chi = clo + 4;
    int b = bh / NH, h = bh % NH;
    int tid = threadIdx.x;
    int lane = tid & 31, warp = tid >> 5;
    int tg = tid >> 4;
    int tc = (tid & 15) * 4;
    int wm = warp & 3, wn = warp >> 2;   // Z1 warp grid: 4 (m) x 2 (n), warp tile 16x32
    int g = lane >> 2, t4 = lane & 3;

    // W1^T fp16 (one-time)
    for (int i = tid; i < 4096; i += 256) {
        int d = i >> 6, e = i & 63;
        sW1t[e*TP + d] = __float2half_rn(W1g[h*4096 + i]);
    }
    if (tid < 64) {
        sGw[tid] = tttw[h*64 + tid];
        sGb[tid] = tttb[h*64 + tid];
        sB1[tid] = b1g[h*64 + tid];
    }
    __syncthreads();

    const size_t rs = 3*CC;
    const __half* kbase = qkv + (size_t)b*NN*rs + 1*CC + h*HD;
    const __half* vbase = qkv + (size_t)b*NN*rs + 2*CC + h*HD;

    uint32_t pK = smaddr(sK16);
    uint32_t pW = smaddr(sW1t);
    int aR = (wm*16 + (lane & 15))*TP + (lane >> 4)*8;
    int bR = (wn*32 + (lane >> 4)*8 + (lane & 7))*TP + ((lane >> 3) & 1)*8;

    float accW[4][4];
#pragma unroll
    for (int i = 0; i < 4; i++)
#pragma unroll
        for (int j = 0; j < 4; j++) accW[i][j] = 0.f;
    float accB[4] = {0.f, 0.f, 0.f, 0.f};

    for (int c = clo; c < chi; c++) {
        int n0 = c * 64;
        // K: fp16 tile + fp32 copy (512 16B segs -> 2/thread)
        for (int t = tid; t < 512; t += 256) {
            int n = t >> 3, s = t & 7;
            uint4 kv = *(const uint4*)&kbase[(size_t)(n0+n)*rs + s*8];
            *(uint4*)&sK16[n*TP + s*8] = kv;
            const __half2* h2 = (const __half2*)&kv;
            float* dst = &sKf[n*64 + s*8];
#pragma unroll
            for (int q = 0; q < 4; q++) {
                float2 f = __half22float2(h2[q]);
                dst[q*2] = f.x; dst[q*2+1] = f.y;
            }
        }
        for (int i = tid; i < 2048; i += 256) {
            int n = i >> 5, e2 = (i & 31) * 2;
            float2 vf = __half22float2(*(const __half2*)&vbase[(size_t)(n0+n)*rs + e2]);
            sV[n*64 + e2] = vf.x; sV[n*64 + e2 + 1] = vf.y;
        }
        if (tid < 64) sEta[tid] = eta[(size_t)bh*NN + n0 + tid];
        __syncthreads();

        // Z1 = K @ W1 (mma), +b1 at store
        {
            float zacc[4][4];
#pragma unroll
            for (int i = 0; i < 4; i++)
#pragma unroll
                for (int j = 0; j < 4; j++) zacc[i][j] = 0.f;
#pragma unroll
            for (int ks = 0; ks < 4; ks++) {
                int kof = ks*16;
                uint32_t a[4], bf[4][2];
                ldm_x4(a, pK + (aR + kof)*2);
#pragma unroll
                for (int p = 0; p < 2; p++) {
                    uint32_t r[4];
                    ldm_x4(r, pW + (bR + p*16*TP + kof)*2);
                    bf[2*p][0] = r[0]; bf[2*p][1] = r[1];
                    bf[2*p+1][0] = r[2]; bf[2*p+1][1] = r[3];
                }
#pragma unroll
                for (int nt = 0; nt < 4; nt++) mma16816(zacc[nt], a, bf[nt]);
            }
#pragma unroll
            for (int nt = 0; nt < 4; nt++) {
#pragma unroll
                for (int hf = 0; hf < 2; hf++) {
                    int r = wm*16 + g + hf*8;
                    int cc = wn*32 + nt*8 + t4*2;
                    sZ[r*64 + cc]     = zacc[nt][hf*2]     + sB1[cc];
                    sZ[r*64 + cc + 1] = zacc[nt][hf*2 + 1] + sB1[cc + 1];
                }
            }
        }
        __syncthreads();

        // fused LN-L2 backward -> eg in sZ (fp32)
        for (int j = 0; j < 8; j++) {
            int n = warp + 8*j;
            float z0 = sZ[n*64 + lane], z1 = sZ[n*64 + lane + 32];
            float mu = warpsum(z0 + z1) * (1.0f/64);
            float d0 = z0 - mu, d1 = z1 - mu;
            float var = warpsum(d0*d0 + d1*d1) * (1.0f/64);
            float rstd = rsqrtf(var + 1e-6f);
            float xh0 = d0*rstd, xh1 = d1*rstd;
            float t0 = sV[n*64 + lane]      - sKf[n*64 + lane];
            float t1 = sV[n*64 + lane + 32] - sKf[n*64 + lane + 32];
            float g0 = sGw[lane], g1 = sGw[lane + 32];
            float gho0 = (g0*xh0 + sGb[lane]      - t0) * g0;
            float gho1 = (g1*xh1 + sGb[lane + 32] - t1) * g1;
            float sg  = warpsum(gho0 + gho1);
            float sgx = warpsum(gho0*xh0 + gho1*xh1);
            float e = sEta[n];
            float inv = rstd * (1.0f/64) * e;
            sZ[n*64 + lane]      = (64.f*gho0 - sg - xh0*sgx) * inv;
            sZ[n*64 + lane + 32] = (64.f*gho1 - sg - xh1*sgx) * inv;
        }
        __syncthreads();

        // accW += K^T @ eg (fp32 FMA)
        for (int n = 0; n < 64; n++) {
            float4 k4 = *(const float4*)&sKf[n*64 + tg*4];
            float4 e4 = *(const float4*)&sZ[n*64 + tc];
            const float* kk = (const float*)&k4;
            const float* ee = (const float*)&e4;
#pragma unroll
            for (int i = 0; i < 4; i++)
#pragma unroll
                for (int j = 0; j < 4; j++) accW[i][j] += kk[i] * ee[j];
            if (tg == 0) {
#pragma unroll
                for (int j = 0; j < 4; j++) accB[j] += ee[j];
            }
        }
        __syncthreads();
    }

    float* base = dWdb + (size_t)bh*DWDB;
#pragma unroll
    for (int i = 0; i < 4; i++)
#pragma unroll
        for (int j = 0; j < 4; j++)
            atomicAdd(&base[(tg*4+i)*64 + tc + j], accW[i][j]);
    if (tg == 0) {
#pragma unroll
        for (int j = 0; j < 4; j++) atomicAdd(&base[4096 + tc + j], accB[j]);
    }
}

// ---------------- w1bar: W1_bar^T fp16 + b1_bar (192 blocks) ----------------
__global__ void __launch_bounds__(256) w1bar_kernel(
    const float* __restrict__ W1g, const float* __restrict__ b1g,
    float* __restrict__ dWdb, __half* __restrict__ w1bt)
{
    int bh = blockIdx.x, h = bh % NH;
    int tid = threadIdx.x;
    float* base = dWdb + (size_t)bh*DWDB;
    __half* wt = w1bt + (size_t)bh*64*TP;
    for (int i = tid; i < 4096; i += 256) {
        int e = i >> 6, d = i & 63;
        wt[e*TP + d] = __float2half_rn(W1g[h*4096 + d*64 + e] - base[d*64 + e]);
    }
    if (tid < 64) base[4096 + tid] = b1g[h*64 + tid] - base[4096 + tid];
}

// ---------------- TTT pass 2: mma Z = Q@W1_bar + LN out; 8 blocks per (b,h) ----------------
__global__ void __launch_bounds__(256) ttt_p2(
    const __half* __restrict__ qkv,
    const float* __restrict__ tttw, const float* __restrict__ tttb,
    const float* __restrict__ dWdb, const __half* __restrict__ w1bt,
    __half* __restrict__ attn)
{
    extern __shared__ float sm[];
    __half* sW1t = (__half*)sm;              // 64 x TP (2304 floats)
    __half* sQ16 = (__half*)(sm + 2304);     // 64 x TP (2304 floats)
    float* sZ   = sm + HPLANES_F;            // 4096
    float* sGw  = sZ + 4096;                 // 64
    float* sGb  = sGw + 64;
    float* sB1b = sGb + 64;

    int bh = blockIdx.x >> 3, part = blockIdx.x & 7;
    int clo = part*2, chi = clo + 2;
    int b = bh / NH, h = bh % NH;
    int tid = threadIdx.x;
    int lane = tid & 31, warp = tid >> 5;
    int wm = warp & 3, wn = warp >> 2;
    int g = lane >> 2, t4 = lane & 3;

    const __half* wsrc = w1bt + (size_t)bh*64*TP;
    for (int t = tid; t < 576; t += 256)
        *(uint4*)&sW1t[t*8] = *(const uint4*)&wsrc[t*8];
    if (tid < 64) {
        sGw[tid] = tttw[h*64 + tid];
        sGb[tid] = tttb[h*64 + tid];
        sB1b[tid] = dWdb[(size_t)bh*DWDB + 4096 + tid];
    }
    __syncthreads();

    const size_t rs = 3*CC;
    const __half* qbase = qkv + (size_t)b*NN*rs + 0*CC + h*HD;
    uint32_t pQ = smaddr(sQ16);
    uint32_t pW = smaddr(sW1t);
    int aR = (wm*16 + (lane & 15))*TP + (lane >> 4)*8;
    int bR = (wn*32 + (lane >> 4)*8 + (lane & 7))*TP + ((lane >> 3) & 1)*8;

    for (int c = clo; c < chi; c++) {
        int n0 = c * 64;
        for (int t = tid; t < 512; t += 256) {
            int n = t >> 3, s = t & 7;
            *(uint4*)&sQ16[n*TP + s*8] = *(const uint4*)&qbase[(size_t)(n0+n)*rs + s*8];
        }
        __syncthreads();
        {
            float zacc[4][4];
#pragma unroll
            for (int i = 0; i < 4; i++)
#pragma unroll
                for (int j = 0; j < 4; j++) zacc[i][j] = 0.f;
#pragma unroll
            for (int ks = 0; ks < 4; ks++) {
                int kof = ks*16;
                uint32_t a[4], bf[4][2];
                ldm_x4(a, pQ + (aR + kof)*2);
#pragma unroll
                for (int p = 0; p < 2; p++) {
                    uint32_t r[4];
                    ldm_x4(r, pW + (bR + p*16*TP + kof)*2);
                    bf[2*p][0] = r[0]; bf[2*p][1] = r[1];
                    bf[2*p+1][0] = r[2]; bf[2*p+1][1] = r[3];
                }
#pragma unroll
                for (int nt = 0; nt < 4; nt++) mma16816(zacc[nt], a, bf[nt]);
            }
#pragma unroll
            for (int nt = 0; nt < 4; nt++) {
#pragma unroll
                for (int hf = 0; hf < 2; hf++) {
                    int r = wm*16 + g + hf*8;
                    int cc = wn*32 + nt*8 + t4*2;
                    sZ[r*64 + cc]     = zacc[nt][hf*2]     + sB1b[cc];
                    sZ[r*64 + cc + 1] = zacc[nt][hf*2 + 1] + sB1b[cc + 1];
                }
            }
        }
        __syncthreads();
        for (int j = 0; j < 8; j++) {
            int n = warp + 8*j;
            float z0 = sZ[n*64 + lane], z1 = sZ[n*64 + lane + 32];
            float mu = warpsum(z0 + z1) * (1.0f/64);
            float d0 = z0 - mu, d1 = z1 - mu;
            float var = warpsum(d0*d0 + d1*d1) * (1.0f/64);
            float rstd = rsqrtf(var + 1e-6f);
            float q0 = __half2float(sQ16[n*TP + lane]);
            float q1 = __half2float(sQ16[n*TP + lane + 32]);
            float o0 = q0 + sGw[lane]     *d0*rstd + sGb[lane];
            float o1 = q1 + sGw[lane + 32]*d1*rstd + sGb[lane + 32];
            size_t orow = ((size_t)(b*NN + n0 + n))*CC + h*HD;
            attn[orow + lane]      = __float2half_rn(o0);
            attn[orow + lane + 32] = __float2half_rn(o1);
        }
        __syncthreads();
    }
}

// ---------------- launch ----------------
extern "C" void kernel_launch(void* const* d_in, const int* in_sizes, int n_in,
                              void* d_out, int out_size) {
    const float* x      = (const float*)d_in[0];
    const float* qkv_w  = (const float*)d_in[1];
    const float* q_bias = (const float*)d_in[2];
    const float* v_bias = (const float*)d_in[3];
    const float* proj_w = (const float*)d_in[4];
    const float* proj_b = (const float*)d_in[5];
    const float* lr_w   = (const float*)d_in[6];
    const float* lr_b   = (const float*)d_in[7];
    const float* W1     = (const float*)d_in[8];
    const float* b1     = (const float*)d_in[9];
    const float* ttt_w  = (const float*)d_in[10];
    const float* ttt_b  = (const float*)d_in[11];
    const float* n1w    = (const float*)d_in[12];
    const float* n1b    = (const float*)d_in[13];
    const float* n2w    = (const float*)d_in[14];
    const float* n2b    = (const float*)d_in[15];
    const float* fc1_w  = (const float*)d_in[16];
    const float* fc1_b  = (const float*)d_in[17];
    const float* fc2_w  = (const float*)d_in[18];
    const float* fc2_b  = (const float*)d_in[19];
    float* out = (float*)d_out;

    float *etap, *x2, *qbias, *dWdbp;
    __half *qkvp, *hp, *attnp, *actp, *wq, *wp, *w1, *w2, *w1btp;
    cudaGetSymbolAddress((void**)&qkvp,  g_qkv);
    cudaGetSymbolAddress((void**)&etap,  g_eta);
    cudaGetSymbolAddress((void**)&x2,    g_x2);
    cudaGetSymbolAddress((void**)&qbias, g_qkvbias);
    cudaGetSymbolAddress((void**)&dWdbp, g_dWdb);
    cudaGetSymbolAddress((void**)&w1btp, g_w1bt);
    cudaGetSymbolAddress((void**)&hp,    g_h);
    cudaGetSymbolAddress((void**)&attnp, g_attn);
    cudaGetSymbolAddress((void**)&actp,  g_act);
    cudaGetSymbolAddress((void**)&wq,    g_wq);
    cudaGetSymbolAddress((void**)&wp,    g_wp);
    cudaGetSymbolAddress((void**)&w1,    g_w1);
    cudaGetSymbolAddress((void**)&w2,    g_w2);

    const int P1_SMEM = (HPLANES_F + 3*4096 + 256) * 4;   // 68608 B
    const int P2_SMEM = (HPLANES_F + 4096 + 192) * 4;     // 35584 B
    cudaFuncSetAttribute(ttt_p1, cudaFuncAttributeMaxDynamicSharedMemorySize, P1_SMEM);
    cudaFuncSetAttribute(ttt_p2, cudaFuncAttributeMaxDynamicSharedMemorySize, P2_SMEM);
    cudaFuncSetAttribute(gemm_mma<1>, cudaFuncAttributeMaxDynamicSharedMemorySize, GEMM_SMEM);
    cudaFuncSetAttribute(gemm_mma<2>, cudaFuncAttributeMaxDynamicSharedMemorySize, GEMM_SMEM);
    cudaFuncSetAttribute(gemm_mma<3>, cudaFuncAttributeMaxDynamicSharedMemorySize, GEMM_SMEM);

    convert_w<<<(WTOT + 3*CC + 255)/256, 256>>>(
        qkv_w, proj_w, fc1_w, fc2_w, q_bias, v_bias, wq, wp, w1, w2, qbias);
    cudaMemsetAsync(dWdbp, 0, (size_t)BB*NH*DWDB*sizeof(float));

    // LN1 + eta
    ln_kernel<<<ROWS/8, 256>>>(x, n1w, n1b, lr_w, lr_b, hp, etap);
    // qkv = h @ qkv_w^T + qkvbias  (fp16 out)
    gemm_mma<3><<<dim3(3*CC/BN, ROWS/BM), GTHREADS, GEMM_SMEM>>>(
        hp, wq, qbias, nullptr, nullptr, qkvp, ROWS, 3*CC, CC);
    // TTT
    ttt_p1<<<BB*NH*4, 256, P1_SMEM>>>(qkvp, etap, W1, b1, ttt_w, ttt_b, dWdbp);
    w1bar_kernel<<<BB*NH, 256>>>(W1, b1, dWdbp, w1btp);
    ttt_p2<<<BB*NH*8, 256, P2_SMEM>>>(qkvp, ttt_w, ttt_b, dWdbp, w1btp, attnp);
    // x2 = x + attn @ proj_w^T + proj_b
    gemm_mma<1><<<dim3(CC/BN, ROWS/BM), GTHREADS, GEMM_SMEM>>>(
        attnp, wp, proj_b, x, x2, nullptr, ROWS, CC, CC);
    // LN2
    ln_kernel<<<ROWS/8, 256>>>(x2, n2w, n2b, nullptr, nullptr, hp, nullptr);
    // act = gelu(h2 @ fc1_w^T + fc1_b)
    gemm_mma<2><<<dim3(4*CC/BN, ROWS/BM), GTHREADS, GEMM_SMEM>>>(
        hp, w1, fc1_b, nullptr, nullptr, actp, ROWS, 4*CC, CC);
    // out = x2 + act @ fc2_w^T + fc2_b
    gemm_mma<1><<<dim3(CC/BN, ROWS/BM), GTHREADS, GEMM_SMEM>>>(
        actp, w2, fc2_b, x2, out, nullptr, ROWS, CC, 4*CC);
}